// round 1
// baseline (speedup 1.0000x reference)
#include <cuda_runtime.h>
#include <cuda_bf16.h>

#define BATCH   2048
#define NTOK    49
#define CH      512
#define NHEADS  4
#define KDIM    32
#define DV      128
#define QO      192      // 2*KD + D
#define EPS     1e-5f
#define YST     196      // padded row stride for y (q|k|v) in smem
#define WST     196      // padded row stride for transposed weight chunk
#define KCHUNK  16
#define NKCH    8        // 128 / 16

// -------- global scratch for h = relu(concat(outs)) --------
__device__ float g_h[(size_t)BATCH * NTOK * CH];

// ==================== Phase A: cascaded heads ====================

struct __align__(16) SmemA {
    float feat[NTOK * 128];      // 6272 floats  (16B aligned)
    float y[NTOK * YST];         // 9604 floats  (offset mult of 4 floats)
    float q[NTOK * KDIM];        // 1568
    float w[KCHUNK * WST];       // 3136  transposed chunk [kk][o]
    float attn[2452];            // 49*49 padded (+ slack for guarded OOB reads)
    float dww[25 * 32];          // conv weights transposed [tap][c]
    float qscale[QO];
    float qbias[QO];
    float dws[KDIM], dwb[KDIM];
    float ab[NHEADS * NTOK];
    unsigned char bidx[NTOK * NTOK];
};

__global__ void __launch_bounds__(256) cascade_kernel(
    const float* __restrict__ x,      const float* __restrict__ qkv_w,
    const float* __restrict__ qkv_g,  const float* __restrict__ qkv_b,
    const float* __restrict__ qkv_m,  const float* __restrict__ qkv_v,
    const float* __restrict__ dw_w,   const float* __restrict__ dw_g,
    const float* __restrict__ dw_b,   const float* __restrict__ dw_m,
    const float* __restrict__ dw_v,   const float* __restrict__ attn_bias,
    const int* __restrict__ bias_idxs)
{
    extern __shared__ unsigned char smem_raw[];
    SmemA& s = *reinterpret_cast<SmemA*>(smem_raw);
    const int t    = threadIdx.x;
    const int b    = blockIdx.x;
    const int lane = t & 31;
    const int warp = t >> 5;
    const float scale = rsqrtf((float)KDIM);

    // one-time loads
    for (int j = t; j < NTOK * NTOK; j += 256) s.bidx[j] = (unsigned char)bias_idxs[j];
    for (int j = t; j < NHEADS * NTOK; j += 256) s.ab[j] = attn_bias[j];
    for (int j = t; j < NTOK * 128; j += 256) {
        int n = j >> 7, d = j & 127;
        s.feat[j] = x[(size_t)b * NTOK * CH + n * CH + d];
    }
    __syncthreads();

    for (int head = 0; head < NHEADS; ++head) {
        // ---- feat += chunk[head] (head>0) ----
        if (head > 0) {
            for (int j = t; j < NTOK * 128; j += 256) {
                int n = j >> 7, d = j & 127;
                s.feat[j] += x[(size_t)b * NTOK * CH + n * CH + head * 128 + d];
            }
        }
        // ---- BN folds ----
        if (t < QO) {
            float sc = qkv_g[head * QO + t] * rsqrtf(qkv_v[head * QO + t] + EPS);
            s.qscale[t] = sc;
            s.qbias[t]  = qkv_b[head * QO + t] - qkv_m[head * QO + t] * sc;
        } else if (t < QO + KDIM) {
            int c = t - QO;
            float sc = dw_g[head * KDIM + c] * rsqrtf(dw_v[head * KDIM + c] + EPS);
            s.dws[c] = sc;
            s.dwb[c] = dw_b[head * KDIM + c] - dw_m[head * KDIM + c] * sc;
        }
        for (int j = t; j < KDIM * 25; j += 256) {
            int c = j / 25, tap = j % 25;
            s.dww[tap * 32 + c] = dw_w[(head * KDIM + c) * 25 + tap];
        }
        __syncthreads();

        // ---- qkv GEMM: y[n][o] = sum_k feat[n][k] * w[o][k], BN fold on store ----
        float acc[5][8];
        #pragma unroll
        for (int j = 0; j < 5; ++j)
            #pragma unroll
            for (int q = 0; q < 8; ++q) acc[j][q] = 0.f;

        const float* wg = qkv_w + (size_t)head * QO * 128;
        for (int kc = 0; kc < NKCH; ++kc) {
            #pragma unroll
            for (int r = 0; r < 12; ++r) {        // stage 192x16 transposed
                int idx = t + r * 256;
                int o = idx >> 4, kk = idx & 15;
                s.w[kk * WST + o] = wg[o * 128 + kc * KCHUNK + kk];
            }
            __syncthreads();
            #pragma unroll
            for (int j = 0; j < 5; ++j) {
                int tile = t + j * 256;
                if (tile < 1200) {
                    int nt = tile / 48, ot = tile % 48;
                    int n0 = nt * 2, o0 = ot * 4;
                    const float* f0p = &s.feat[n0 * 128 + kc * KCHUNK];
                    const float* f1p = f0p + 128;   // row 49 read is guarded at store
                    #pragma unroll
                    for (int k4 = 0; k4 < 4; ++k4) {
                        float fav[4], fbv[4];
                        *reinterpret_cast<float4*>(fav) = *reinterpret_cast<const float4*>(f0p + k4 * 4);
                        *reinterpret_cast<float4*>(fbv) = *reinterpret_cast<const float4*>(f1p + k4 * 4);
                        #pragma unroll
                        for (int kk = 0; kk < 4; ++kk) {
                            float4 w4 = *reinterpret_cast<const float4*>(&s.w[(k4 * 4 + kk) * WST + o0]);
                            float f0 = fav[kk], f1 = fbv[kk];
                            acc[j][0] += f0 * w4.x; acc[j][1] += f0 * w4.y;
                            acc[j][2] += f0 * w4.z; acc[j][3] += f0 * w4.w;
                            acc[j][4] += f1 * w4.x; acc[j][5] += f1 * w4.y;
                            acc[j][6] += f1 * w4.z; acc[j][7] += f1 * w4.w;
                        }
                    }
                }
            }
            __syncthreads();
        }
        #pragma unroll
        for (int j = 0; j < 5; ++j) {           // epilogue: BN -> s.y
            int tile = t + j * 256;
            if (tile < 1200) {
                int nt = tile / 48, ot = tile % 48;
                int n0 = nt * 2, o0 = ot * 4;
                #pragma unroll
                for (int q = 0; q < 4; ++q) {
                    int o = o0 + q;
                    s.y[n0 * YST + o] = acc[j][q] * s.qscale[o] + s.qbias[o];
                    if (n0 + 1 < NTOK)
                        s.y[(n0 + 1) * YST + o] = acc[j][4 + q] * s.qscale[o] + s.qbias[o];
                }
            }
        }
        __syncthreads();

        // ---- depthwise 5x5 conv on q (+BN) ----
        for (int idx = t; idx < NTOK * KDIM; idx += 256) {
            int n = idx >> 5, c = idx & 31;
            int r = n / 7, sc_ = n % 7;
            float sum = 0.f;
            #pragma unroll
            for (int a = 0; a < 5; ++a) {
                int rr = r + a - 2;
                if ((unsigned)rr < 7u) {
                    #pragma unroll
                    for (int bb = 0; bb < 5; ++bb) {
                        int ss = sc_ + bb - 2;
                        if ((unsigned)ss < 7u)
                            sum += s.y[(rr * 7 + ss) * YST + c] * s.dww[(a * 5 + bb) * 32 + c];
                    }
                }
            }
            s.q[n * 32 + c] = sum * s.dws[c] + s.dwb[c];
        }
        __syncthreads();

        // ---- attention scores + bias ----
        for (int p = t; p < NTOK * NTOK; p += 256) {
            int n = p / 49, m = p % 49;
            const float4* qp = reinterpret_cast<const float4*>(&s.q[n * 32]);
            const float4* kp = reinterpret_cast<const float4*>(&s.y[m * YST + KDIM]);
            float sum = 0.f;
            #pragma unroll
            for (int k4 = 0; k4 < 8; ++k4) {
                float4 a = qp[k4], bb = kp[k4];
                sum += a.x * bb.x + a.y * bb.y + a.z * bb.z + a.w * bb.w;
            }
            s.attn[p] = sum * scale + s.ab[head * NTOK + s.bidx[p]];
        }
        __syncthreads();

        // ---- softmax (one warp per row) ----
        for (int r = warp; r < NTOK; r += 8) {
            float a = s.attn[r * 49 + lane];
            bool hasb = (lane + 32) < 49;
            float bv = hasb ? s.attn[r * 49 + lane + 32] : -1e30f;
            float mx = fmaxf(a, bv);
            #pragma unroll
            for (int off = 16; off > 0; off >>= 1)
                mx = fmaxf(mx, __shfl_xor_sync(0xffffffffu, mx, off));
            float ea = __expf(a - mx);
            float eb = hasb ? __expf(bv - mx) : 0.f;
            float sm = ea + eb;
            #pragma unroll
            for (int off = 16; off > 0; off >>= 1)
                sm += __shfl_xor_sync(0xffffffffu, sm, off);
            float inv = __frcp_rn(sm);
            s.attn[r * 49 + lane] = ea * inv;
            if (hasb) s.attn[r * 49 + lane + 32] = eb * inv;
        }
        __syncthreads();

        // ---- feat_new = attn @ v ; write relu to g_h, raw to s.feat ----
        float fac[4][8];
        #pragma unroll
        for (int j = 0; j < 4; ++j)
            #pragma unroll
            for (int q = 0; q < 8; ++q) fac[j][q] = 0.f;

        #pragma unroll
        for (int j = 0; j < 4; ++j) {
            int tile = t + j * 256;
            if (tile < 800) {
                int nt = tile / 32, dt = tile % 32;
                int n0 = nt * 2, d0 = dt * 4;
                #pragma unroll 7
                for (int m = 0; m < NTOK; ++m) {
                    float a0 = s.attn[n0 * 49 + m];
                    float a1 = s.attn[n0 * 49 + 49 + m];   // row 49 read guarded at store
                    float4 v4 = *reinterpret_cast<const float4*>(&s.y[m * YST + 64 + d0]);
                    fac[j][0] += a0 * v4.x; fac[j][1] += a0 * v4.y;
                    fac[j][2] += a0 * v4.z; fac[j][3] += a0 * v4.w;
                    fac[j][4] += a1 * v4.x; fac[j][5] += a1 * v4.y;
                    fac[j][6] += a1 * v4.z; fac[j][7] += a1 * v4.w;
                }
            }
        }
        __syncthreads();   // all attn/y reads done before overwriting feat
        #pragma unroll
        for (int j = 0; j < 4; ++j) {
            int tile = t + j * 256;
            if (tile < 800) {
                int nt = tile / 32, dt = tile % 32;
                int n0 = nt * 2, d0 = dt * 4;
                float4 f0 = make_float4(fac[j][0], fac[j][1], fac[j][2], fac[j][3]);
                *reinterpret_cast<float4*>(&s.feat[n0 * 128 + d0]) = f0;
                float4 r0 = make_float4(fmaxf(f0.x, 0.f), fmaxf(f0.y, 0.f),
                                        fmaxf(f0.z, 0.f), fmaxf(f0.w, 0.f));
                *reinterpret_cast<float4*>(&g_h[((size_t)b * NTOK + n0) * CH + head * 128 + d0]) = r0;
                if (n0 + 1 < NTOK) {
                    float4 f1 = make_float4(fac[j][4], fac[j][5], fac[j][6], fac[j][7]);
                    *reinterpret_cast<float4*>(&s.feat[(n0 + 1) * 128 + d0]) = f1;
                    float4 r1 = make_float4(fmaxf(f1.x, 0.f), fmaxf(f1.y, 0.f),
                                            fmaxf(f1.z, 0.f), fmaxf(f1.w, 0.f));
                    *reinterpret_cast<float4*>(&g_h[((size_t)b * NTOK + n0 + 1) * CH + head * 128 + d0]) = r1;
                }
            }
        }
        __syncthreads();
    }
}

// ==================== Phase B: projection GEMM (packed f32x2) ====================

#define BM 128
#define BN 64
#define BK 16
#define AST 20
#define BST 20

__device__ __forceinline__ unsigned long long ffma2(unsigned long long a,
                                                    unsigned long long b,
                                                    unsigned long long c) {
    unsigned long long d;
    asm("fma.rn.f32x2 %0, %1, %2, %3;" : "=l"(d) : "l"(a), "l"(b), "l"(c));
    return d;
}

__device__ __forceinline__ float sum2(unsigned long long u) {
    float lo = __uint_as_float((unsigned)(u & 0xffffffffull));
    float hi = __uint_as_float((unsigned)(u >> 32));
    return lo + hi;
}

__global__ void __launch_bounds__(256) proj_kernel(
    const float* __restrict__ proj_w, const float* __restrict__ proj_g,
    const float* __restrict__ proj_b, const float* __restrict__ proj_m,
    const float* __restrict__ proj_v, float* __restrict__ out)
{
    __shared__ float sA[BM * AST];
    __shared__ float sB[BN * BST];
    __shared__ float sPs[BN], sPb[BN];

    const int t   = threadIdx.x;
    const int bn  = blockIdx.x;     // 0..7
    const int bm  = blockIdx.y;     // 0..783
    const int row0 = bm * BM;
    const int col0 = bn * BN;

    if (t < BN) {
        int o = col0 + t;
        float sc = proj_g[o] * rsqrtf(proj_v[o] + EPS);
        sPs[t] = sc;
        sPb[t] = proj_b[o] - proj_m[o] * sc;
    }

    const int tm = t >> 4;          // 0..15
    const int to = t & 15;          // 0..15
    const int m0 = tm * 8, o0 = to * 4;

    unsigned long long acc[8][4];
    #pragma unroll
    for (int mi = 0; mi < 8; ++mi)
        #pragma unroll
        for (int oi = 0; oi < 4; ++oi) acc[mi][oi] = 0ull;

    for (int kc = 0; kc < 32; ++kc) {
        __syncthreads();
        #pragma unroll
        for (int r = 0; r < 8; ++r) {
            int idx = t + r * 256;
            int m = idx >> 4, k = idx & 15;
            sA[m * AST + k] = g_h[(size_t)(row0 + m) * 512 + kc * 16 + k];
        }
        #pragma unroll
        for (int r = 0; r < 4; ++r) {
            int idx = t + r * 256;
            int o = idx >> 4, k = idx & 15;
            sB[o * BST + k] = proj_w[(size_t)(col0 + o) * 512 + kc * 16 + k];
        }
        __syncthreads();
        #pragma unroll
        for (int k0 = 0; k0 < 16; k0 += 4) {
            ulonglong2 bv[4];
            #pragma unroll
            for (int oi = 0; oi < 4; ++oi)
                bv[oi] = *reinterpret_cast<const ulonglong2*>(&sB[(o0 + oi) * BST + k0]);
            #pragma unroll
            for (int mi = 0; mi < 8; ++mi) {
                ulonglong2 av = *reinterpret_cast<const ulonglong2*>(&sA[(m0 + mi) * AST + k0]);
                #pragma unroll
                for (int oi = 0; oi < 4; ++oi) {
                    acc[mi][oi] = ffma2(av.x, bv[oi].x, acc[mi][oi]);
                    acc[mi][oi] = ffma2(av.y, bv[oi].y, acc[mi][oi]);
                }
            }
        }
    }

    #pragma unroll
    for (int mi = 0; mi < 8; ++mi) {
        int row = row0 + m0 + mi;
        float res[4];
        #pragma unroll
        for (int oi = 0; oi < 4; ++oi)
            res[oi] = sum2(acc[mi][oi]) * sPs[o0 + oi] + sPb[o0 + oi];
        *reinterpret_cast<float4*>(&out[(size_t)row * 512 + col0 + o0]) =
            make_float4(res[0], res[1], res[2], res[3]);
    }
}

// ==================== launch ====================

extern "C" void kernel_launch(void* const* d_in, const int* in_sizes, int n_in,
                              void* d_out, int out_size) {
    const float* x         = (const float*)d_in[0];
    const float* qkv_w     = (const float*)d_in[1];
    const float* qkv_g     = (const float*)d_in[2];
    const float* qkv_b     = (const float*)d_in[3];
    const float* qkv_m     = (const float*)d_in[4];
    const float* qkv_v     = (const float*)d_in[5];
    const float* dw_w      = (const float*)d_in[6];
    const float* dw_g      = (const float*)d_in[7];
    const float* dw_b      = (const float*)d_in[8];
    const float* dw_m      = (const float*)d_in[9];
    const float* dw_v      = (const float*)d_in[10];
    const float* proj_w    = (const float*)d_in[11];
    const float* proj_g    = (const float*)d_in[12];
    const float* proj_b    = (const float*)d_in[13];
    const float* proj_m    = (const float*)d_in[14];
    const float* proj_v    = (const float*)d_in[15];
    const float* attn_bias = (const float*)d_in[16];
    const int*   bias_idxs = (const int*)d_in[17];
    float* out = (float*)d_out;

    cudaFuncSetAttribute(cascade_kernel,
                         cudaFuncAttributeMaxDynamicSharedMemorySize,
                         (int)sizeof(SmemA));

    cascade_kernel<<<BATCH, 256, sizeof(SmemA)>>>(
        x, qkv_w, qkv_g, qkv_b, qkv_m, qkv_v,
        dw_w, dw_g, dw_b, dw_m, dw_v, attn_bias, bias_idxs);

    proj_kernel<<<dim3(8, 784), 256>>>(proj_w, proj_g, proj_b, proj_m, proj_v, out);
}

// round 2
// speedup vs baseline: 2.2163x; 2.2163x over previous
#include <cuda_runtime.h>
#include <cuda_bf16.h>

#define BATCH   2048
#define NTOK    49
#define CH      512
#define NHEADS  4
#define KDIM    32
#define DV      128
#define QO      192      // 2*KD + D
#define EPS     1e-5f
#define YST     196      // padded row stride for y (q|k|v) in smem
#define WST     196      // padded row stride for transposed weight chunk
#define KCHUNK  16
#define NKCH    8        // 128 / 16

// -------- global scratch: h = relu(concat(outs)) as bf16 hi/lo, split proj_w --------
__device__ __align__(16) __nv_bfloat16 g_h_hi[(size_t)BATCH * NTOK * CH];
__device__ __align__(16) __nv_bfloat16 g_h_lo[(size_t)BATCH * NTOK * CH];
__device__ __align__(16) __nv_bfloat16 g_w_hi[CH * CH];
__device__ __align__(16) __nv_bfloat16 g_w_lo[CH * CH];

// ==================== prep: split proj_w into bf16 hi/lo ====================
__global__ void wsplit_kernel(const float* __restrict__ w) {
    int i = blockIdx.x * 256 + threadIdx.x;      // 512*512 / 256 = 1024 blocks
    float v = w[i];
    __nv_bfloat16 h = __float2bfloat16(v);
    g_w_hi[i] = h;
    g_w_lo[i] = __float2bfloat16(v - __bfloat162float(h));
}

// ==================== Phase A: cascaded heads ====================

struct __align__(16) SmemA {
    float feat[NTOK * 128];
    float y[NTOK * YST];
    float q[NTOK * KDIM];
    float w[KCHUNK * WST];
    float attn[2452];
    float dww[25 * 32];
    float qscale[QO];
    float qbias[QO];
    float dws[KDIM], dwb[KDIM];
    float ab[NHEADS * NTOK];
    unsigned char bidx[NTOK * NTOK];
};

__global__ void __launch_bounds__(256, 2) cascade_kernel(
    const float* __restrict__ x,      const float* __restrict__ qkv_w,
    const float* __restrict__ qkv_g,  const float* __restrict__ qkv_b,
    const float* __restrict__ qkv_m,  const float* __restrict__ qkv_v,
    const float* __restrict__ dw_w,   const float* __restrict__ dw_g,
    const float* __restrict__ dw_b,   const float* __restrict__ dw_m,
    const float* __restrict__ dw_v,   const float* __restrict__ attn_bias,
    const int* __restrict__ bias_idxs)
{
    extern __shared__ unsigned char smem_raw[];
    SmemA& s = *reinterpret_cast<SmemA*>(smem_raw);
    const int t    = threadIdx.x;
    const int b    = blockIdx.x;
    const int lane = t & 31;
    const int warp = t >> 5;
    const float scale = rsqrtf((float)KDIM);

    for (int j = t; j < NTOK * NTOK; j += 256) s.bidx[j] = (unsigned char)bias_idxs[j];
    for (int j = t; j < NHEADS * NTOK; j += 256) s.ab[j] = attn_bias[j];
    for (int j = t; j < NTOK * 128; j += 256) {
        int n = j >> 7, d = j & 127;
        s.feat[j] = x[(size_t)b * NTOK * CH + n * CH + d];
    }
    __syncthreads();

    for (int head = 0; head < NHEADS; ++head) {
        if (head > 0) {
            for (int j = t; j < NTOK * 128; j += 256) {
                int n = j >> 7, d = j & 127;
                s.feat[j] += x[(size_t)b * NTOK * CH + n * CH + head * 128 + d];
            }
        }
        if (t < QO) {
            float sc = qkv_g[head * QO + t] * rsqrtf(qkv_v[head * QO + t] + EPS);
            s.qscale[t] = sc;
            s.qbias[t]  = qkv_b[head * QO + t] - qkv_m[head * QO + t] * sc;
        } else if (t < QO + KDIM) {
            int c = t - QO;
            float sc = dw_g[head * KDIM + c] * rsqrtf(dw_v[head * KDIM + c] + EPS);
            s.dws[c] = sc;
            s.dwb[c] = dw_b[head * KDIM + c] - dw_m[head * KDIM + c] * sc;
        }
        for (int j = t; j < KDIM * 25; j += 256) {
            int c = j / 25, tap = j % 25;
            s.dww[tap * 32 + c] = dw_w[(head * KDIM + c) * 25 + tap];
        }
        __syncthreads();

        // ---- qkv GEMM ----
        float acc[5][8];
        #pragma unroll
        for (int j = 0; j < 5; ++j)
            #pragma unroll
            for (int q = 0; q < 8; ++q) acc[j][q] = 0.f;

        const float* wg = qkv_w + (size_t)head * QO * 128;
        for (int kc = 0; kc < NKCH; ++kc) {
            #pragma unroll
            for (int r = 0; r < 12; ++r) {
                int idx = t + r * 256;
                int o = idx >> 4, kk = idx & 15;
                s.w[kk * WST + o] = wg[o * 128 + kc * KCHUNK + kk];
            }
            __syncthreads();
            #pragma unroll
            for (int j = 0; j < 5; ++j) {
                int tile = t + j * 256;
                if (tile < 1200) {
                    int nt = tile / 48, ot = tile % 48;
                    int n0 = nt * 2, o0 = ot * 4;
                    const float* f0p = &s.feat[n0 * 128 + kc * KCHUNK];
                    const float* f1p = f0p + 128;
                    #pragma unroll
                    for (int k4 = 0; k4 < 4; ++k4) {
                        float fav[4], fbv[4];
                        *reinterpret_cast<float4*>(fav) = *reinterpret_cast<const float4*>(f0p + k4 * 4);
                        *reinterpret_cast<float4*>(fbv) = *reinterpret_cast<const float4*>(f1p + k4 * 4);
                        #pragma unroll
                        for (int kk = 0; kk < 4; ++kk) {
                            float4 w4 = *reinterpret_cast<const float4*>(&s.w[(k4 * 4 + kk) * WST + o0]);
                            float f0 = fav[kk], f1 = fbv[kk];
                            acc[j][0] += f0 * w4.x; acc[j][1] += f0 * w4.y;
                            acc[j][2] += f0 * w4.z; acc[j][3] += f0 * w4.w;
                            acc[j][4] += f1 * w4.x; acc[j][5] += f1 * w4.y;
                            acc[j][6] += f1 * w4.z; acc[j][7] += f1 * w4.w;
                        }
                    }
                }
            }
            __syncthreads();
        }
        #pragma unroll
        for (int j = 0; j < 5; ++j) {
            int tile = t + j * 256;
            if (tile < 1200) {
                int nt = tile / 48, ot = tile % 48;
                int n0 = nt * 2, o0 = ot * 4;
                #pragma unroll
                for (int q = 0; q < 4; ++q) {
                    int o = o0 + q;
                    s.y[n0 * YST + o] = acc[j][q] * s.qscale[o] + s.qbias[o];
                    if (n0 + 1 < NTOK)
                        s.y[(n0 + 1) * YST + o] = acc[j][4 + q] * s.qscale[o] + s.qbias[o];
                }
            }
        }
        __syncthreads();

        // ---- depthwise 5x5 conv (+BN) ----
        for (int idx = t; idx < NTOK * KDIM; idx += 256) {
            int n = idx >> 5, c = idx & 31;
            int r = n / 7, sc_ = n % 7;
            float sum = 0.f;
            #pragma unroll
            for (int a = 0; a < 5; ++a) {
                int rr = r + a - 2;
                if ((unsigned)rr < 7u) {
                    #pragma unroll
                    for (int bb = 0; bb < 5; ++bb) {
                        int ss = sc_ + bb - 2;
                        if ((unsigned)ss < 7u)
                            sum += s.y[(rr * 7 + ss) * YST + c] * s.dww[(a * 5 + bb) * 32 + c];
                    }
                }
            }
            s.q[n * 32 + c] = sum * s.dws[c] + s.dwb[c];
        }
        __syncthreads();

        // ---- scores + bias ----
        for (int p = t; p < NTOK * NTOK; p += 256) {
            int n = p / 49, m = p % 49;
            const float4* qp = reinterpret_cast<const float4*>(&s.q[n * 32]);
            const float4* kp = reinterpret_cast<const float4*>(&s.y[m * YST + KDIM]);
            float sum = 0.f;
            #pragma unroll
            for (int k4 = 0; k4 < 8; ++k4) {
                float4 a = qp[k4], bb = kp[k4];
                sum += a.x * bb.x + a.y * bb.y + a.z * bb.z + a.w * bb.w;
            }
            s.attn[p] = sum * scale + s.ab[head * NTOK + s.bidx[p]];
        }
        __syncthreads();

        // ---- softmax ----
        for (int r = warp; r < NTOK; r += 8) {
            float a = s.attn[r * 49 + lane];
            bool hasb = (lane + 32) < 49;
            float bv = hasb ? s.attn[r * 49 + lane + 32] : -1e30f;
            float mx = fmaxf(a, bv);
            #pragma unroll
            for (int off = 16; off > 0; off >>= 1)
                mx = fmaxf(mx, __shfl_xor_sync(0xffffffffu, mx, off));
            float ea = __expf(a - mx);
            float eb = hasb ? __expf(bv - mx) : 0.f;
            float sm = ea + eb;
            #pragma unroll
            for (int off = 16; off > 0; off >>= 1)
                sm += __shfl_xor_sync(0xffffffffu, sm, off);
            float inv = __frcp_rn(sm);
            s.attn[r * 49 + lane] = ea * inv;
            if (hasb) s.attn[r * 49 + lane + 32] = eb * inv;
        }
        __syncthreads();

        // ---- feat_new = attn @ v ----
        float fac[4][8];
        #pragma unroll
        for (int j = 0; j < 4; ++j)
            #pragma unroll
            for (int q = 0; q < 8; ++q) fac[j][q] = 0.f;

        #pragma unroll
        for (int j = 0; j < 4; ++j) {
            int tile = t + j * 256;
            if (tile < 800) {
                int nt = tile / 32, dt = tile % 32;
                int n0 = nt * 2, d0 = dt * 4;
                #pragma unroll 7
                for (int m = 0; m < NTOK; ++m) {
                    float a0 = s.attn[n0 * 49 + m];
                    float a1 = s.attn[n0 * 49 + 49 + m];
                    float4 v4 = *reinterpret_cast<const float4*>(&s.y[m * YST + 64 + d0]);
                    fac[j][0] += a0 * v4.x; fac[j][1] += a0 * v4.y;
                    fac[j][2] += a0 * v4.z; fac[j][3] += a0 * v4.w;
                    fac[j][4] += a1 * v4.x; fac[j][5] += a1 * v4.y;
                    fac[j][6] += a1 * v4.z; fac[j][7] += a1 * v4.w;
                }
            }
        }
        __syncthreads();
        #pragma unroll
        for (int j = 0; j < 4; ++j) {
            int tile = t + j * 256;
            if (tile < 800) {
                int nt = tile / 32, dt = tile % 32;
                int n0 = nt * 2, d0 = dt * 4;
                #pragma unroll
                for (int half = 0; half < 2; ++half) {
                    int n = n0 + half;
                    if (n < NTOK) {
                        float v0 = fac[j][half * 4 + 0], v1 = fac[j][half * 4 + 1];
                        float v2 = fac[j][half * 4 + 2], v3 = fac[j][half * 4 + 3];
                        *reinterpret_cast<float4*>(&s.feat[n * 128 + d0]) =
                            make_float4(v0, v1, v2, v3);
                        float r0 = fmaxf(v0, 0.f), r1 = fmaxf(v1, 0.f);
                        float r2 = fmaxf(v2, 0.f), r3 = fmaxf(v3, 0.f);
                        __nv_bfloat16 h0 = __float2bfloat16(r0), h1 = __float2bfloat16(r1);
                        __nv_bfloat16 h2 = __float2bfloat16(r2), h3 = __float2bfloat16(r3);
                        __nv_bfloat16 l0 = __float2bfloat16(r0 - __bfloat162float(h0));
                        __nv_bfloat16 l1 = __float2bfloat16(r1 - __bfloat162float(h1));
                        __nv_bfloat16 l2 = __float2bfloat16(r2 - __bfloat162float(h2));
                        __nv_bfloat16 l3 = __float2bfloat16(r3 - __bfloat162float(h3));
                        __nv_bfloat162 hp0 = __halves2bfloat162(h0, h1);
                        __nv_bfloat162 hp1 = __halves2bfloat162(h2, h3);
                        __nv_bfloat162 lp0 = __halves2bfloat162(l0, l1);
                        __nv_bfloat162 lp1 = __halves2bfloat162(l2, l3);
                        size_t off = ((size_t)b * NTOK + n) * CH + head * 128 + d0;
                        uint2 uh, ul;
                        uh.x = *reinterpret_cast<unsigned*>(&hp0);
                        uh.y = *reinterpret_cast<unsigned*>(&hp1);
                        ul.x = *reinterpret_cast<unsigned*>(&lp0);
                        ul.y = *reinterpret_cast<unsigned*>(&lp1);
                        *reinterpret_cast<uint2*>(&g_h_hi[off]) = uh;
                        *reinterpret_cast<uint2*>(&g_h_lo[off]) = ul;
                    }
                }
            }
        }
        __syncthreads();
    }
}

// ==================== Phase B: projection via bf16 mma (3-term split) ====================

#define PM 128
#define PN 64
#define PKC 32
#define AS 40    // padded smem row stride (elems) -> 80B, conflict-free ldmatrix

__device__ __forceinline__ unsigned s2u(const void* p) {
    return (unsigned)__cvta_generic_to_shared(p);
}

__device__ __forceinline__ void ldsm_x4(unsigned* r, unsigned addr) {
    asm volatile("ldmatrix.sync.aligned.m8n8.x4.shared.b16 {%0,%1,%2,%3}, [%4];"
        : "=r"(r[0]), "=r"(r[1]), "=r"(r[2]), "=r"(r[3]) : "r"(addr));
}

__device__ __forceinline__ void mma16816(float* c, const unsigned* a, const unsigned* b) {
    asm volatile("mma.sync.aligned.m16n8k16.row.col.f32.bf16.bf16.f32 "
        "{%0,%1,%2,%3}, {%4,%5,%6,%7}, {%8,%9}, {%0,%1,%2,%3};"
        : "+f"(c[0]), "+f"(c[1]), "+f"(c[2]), "+f"(c[3])
        : "r"(a[0]), "r"(a[1]), "r"(a[2]), "r"(a[3]), "r"(b[0]), "r"(b[1]));
}

__global__ void __launch_bounds__(256, 2) proj_mma_kernel(
    const float* __restrict__ proj_g, const float* __restrict__ proj_b,
    const float* __restrict__ proj_m, const float* __restrict__ proj_v,
    float* __restrict__ out)
{
    __shared__ __align__(16) __nv_bfloat16 sAh[PM * AS];
    __shared__ __align__(16) __nv_bfloat16 sAl[PM * AS];
    __shared__ __align__(16) __nv_bfloat16 sBh[PN * AS];
    __shared__ __align__(16) __nv_bfloat16 sBl[PN * AS];
    __shared__ float sPs[PN], sPb[PN];

    const int t = threadIdx.x, lane = t & 31, warp = t >> 5;
    const int row0 = blockIdx.y * PM, col0 = blockIdx.x * PN;

    if (t < PN) {
        int o = col0 + t;
        float sc = proj_g[o] * rsqrtf(proj_v[o] + EPS);
        sPs[t] = sc;
        sPb[t] = proj_b[o] - proj_m[o] * sc;
    }

    const int ar0 = t >> 2;            // 0..63
    const int akk = (t & 3) * 8;       // 0,8,16,24

    float acc[2][4][4];
    #pragma unroll
    for (int mt = 0; mt < 2; ++mt)
        #pragma unroll
        for (int nt = 0; nt < 4; ++nt)
            #pragma unroll
            for (int q = 0; q < 4; ++q) acc[mt][nt][q] = 0.f;

    const int wm = (warp >> 1) * 32, wn = (warp & 1) * 32;
    const int a_r = lane & 15, a_c = (lane >> 4) * 8;
    const int b_r = (lane & 7) + ((lane & 16) ? 8 : 0);
    const int b_c = (lane & 8) ? 8 : 0;

    uint4 rah0, rah1, ral0, ral1, rbh, rbl;
    {   // prefetch chunk 0
        size_t base  = (size_t)(row0 + ar0) * 512 + akk;
        rah0 = *reinterpret_cast<const uint4*>(&g_h_hi[base]);
        ral0 = *reinterpret_cast<const uint4*>(&g_h_lo[base]);
        rah1 = *reinterpret_cast<const uint4*>(&g_h_hi[base + (size_t)64 * 512]);
        ral1 = *reinterpret_cast<const uint4*>(&g_h_lo[base + (size_t)64 * 512]);
        size_t bb = (size_t)(col0 + ar0) * 512 + akk;
        rbh = *reinterpret_cast<const uint4*>(&g_w_hi[bb]);
        rbl = *reinterpret_cast<const uint4*>(&g_w_lo[bb]);
    }

    for (int kc = 0; kc < 16; ++kc) {
        __syncthreads();
        *reinterpret_cast<uint4*>(&sAh[ar0 * AS + akk]) = rah0;
        *reinterpret_cast<uint4*>(&sAl[ar0 * AS + akk]) = ral0;
        *reinterpret_cast<uint4*>(&sAh[(ar0 + 64) * AS + akk]) = rah1;
        *reinterpret_cast<uint4*>(&sAl[(ar0 + 64) * AS + akk]) = ral1;
        *reinterpret_cast<uint4*>(&sBh[ar0 * AS + akk]) = rbh;
        *reinterpret_cast<uint4*>(&sBl[ar0 * AS + akk]) = rbl;
        __syncthreads();
        if (kc < 15) {
            size_t base = (size_t)(row0 + ar0) * 512 + (kc + 1) * PKC + akk;
            rah0 = *reinterpret_cast<const uint4*>(&g_h_hi[base]);
            ral0 = *reinterpret_cast<const uint4*>(&g_h_lo[base]);
            rah1 = *reinterpret_cast<const uint4*>(&g_h_hi[base + (size_t)64 * 512]);
            ral1 = *reinterpret_cast<const uint4*>(&g_h_lo[base + (size_t)64 * 512]);
            size_t bb = (size_t)(col0 + ar0) * 512 + (kc + 1) * PKC + akk;
            rbh = *reinterpret_cast<const uint4*>(&g_w_hi[bb]);
            rbl = *reinterpret_cast<const uint4*>(&g_w_lo[bb]);
        }
        #pragma unroll
        for (int k16 = 0; k16 < 2; ++k16) {
            int kb = k16 * 16;
            unsigned Ah[2][4], Al[2][4], Bh[2][4], Bl[2][4];
            #pragma unroll
            for (int mt = 0; mt < 2; ++mt) {
                ldsm_x4(Ah[mt], s2u(&sAh[(wm + mt * 16 + a_r) * AS + kb + a_c]));
                ldsm_x4(Al[mt], s2u(&sAl[(wm + mt * 16 + a_r) * AS + kb + a_c]));
            }
            #pragma unroll
            for (int g = 0; g < 2; ++g) {
                int br = wn + g * 16 + b_r;
                ldsm_x4(Bh[g], s2u(&sBh[br * AS + kb + b_c]));
                ldsm_x4(Bl[g], s2u(&sBl[br * AS + kb + b_c]));
            }
            #pragma unroll
            for (int mt = 0; mt < 2; ++mt)
                #pragma unroll
                for (int nt = 0; nt < 4; ++nt) {
                    const unsigned* bh = &Bh[nt >> 1][(nt & 1) * 2];
                    const unsigned* bl = &Bl[nt >> 1][(nt & 1) * 2];
                    mma16816(acc[mt][nt], Ah[mt], bh);
                    mma16816(acc[mt][nt], Ah[mt], bl);
                    mma16816(acc[mt][nt], Al[mt], bh);
                }
        }
    }

    // epilogue: BN fold + store
    const int er = lane >> 2, ec = (lane & 3) * 2;
    #pragma unroll
    for (int mt = 0; mt < 2; ++mt)
        #pragma unroll
        for (int nt = 0; nt < 4; ++nt) {
            int cl = wn + nt * 8 + ec;
            float s0 = sPs[cl], s1 = sPs[cl + 1];
            float b0 = sPb[cl], b1 = sPb[cl + 1];
            size_t gr = (size_t)(row0 + wm + mt * 16 + er) * 512 + col0 + cl;
            *reinterpret_cast<float2*>(&out[gr]) =
                make_float2(acc[mt][nt][0] * s0 + b0, acc[mt][nt][1] * s1 + b1);
            *reinterpret_cast<float2*>(&out[gr + (size_t)8 * 512]) =
                make_float2(acc[mt][nt][2] * s0 + b0, acc[mt][nt][3] * s1 + b1);
        }
}

// ==================== launch ====================

extern "C" void kernel_launch(void* const* d_in, const int* in_sizes, int n_in,
                              void* d_out, int out_size) {
    const float* x         = (const float*)d_in[0];
    const float* qkv_w     = (const float*)d_in[1];
    const float* qkv_g     = (const float*)d_in[2];
    const float* qkv_b     = (const float*)d_in[3];
    const float* qkv_m     = (const float*)d_in[4];
    const float* qkv_v     = (const float*)d_in[5];
    const float* dw_w      = (const float*)d_in[6];
    const float* dw_g      = (const float*)d_in[7];
    const float* dw_b      = (const float*)d_in[8];
    const float* dw_m      = (const float*)d_in[9];
    const float* dw_v      = (const float*)d_in[10];
    const float* proj_w    = (const float*)d_in[11];
    const float* proj_g    = (const float*)d_in[12];
    const float* proj_b    = (const float*)d_in[13];
    const float* proj_m    = (const float*)d_in[14];
    const float* proj_v    = (const float*)d_in[15];
    const float* attn_bias = (const float*)d_in[16];
    const int*   bias_idxs = (const int*)d_in[17];
    float* out = (float*)d_out;

    cudaFuncSetAttribute(cascade_kernel,
                         cudaFuncAttributeMaxDynamicSharedMemorySize,
                         (int)sizeof(SmemA));

    wsplit_kernel<<<1024, 256>>>(proj_w);

    cascade_kernel<<<BATCH, 256, sizeof(SmemA)>>>(
        x, qkv_w, qkv_g, qkv_b, qkv_m, qkv_v,
        dw_w, dw_g, dw_b, dw_m, dw_v, attn_bias, bias_idxs);

    proj_mma_kernel<<<dim3(8, 784), 256>>>(proj_g, proj_b, proj_m, proj_v, out);
}

// round 3
// speedup vs baseline: 3.2663x; 1.4737x over previous
#include <cuda_runtime.h>
#include <cuda_bf16.h>

#define BATCH   2048
#define NTOK    49
#define CH      512
#define NHEADS  4
#define KDIM    32
#define DV      128
#define QO      192
#define EPS     1e-5f
#define YST     196
#define ARS     136      // bf16 A row stride (128 + 8 pad)

// -------- global scratch --------
__device__ __align__(16) __nv_bfloat16 g_h_hi[(size_t)BATCH * NTOK * CH];
__device__ __align__(16) __nv_bfloat16 g_h_lo[(size_t)BATCH * NTOK * CH];
__device__ __align__(16) __nv_bfloat16 g_w_hi[CH * CH];
__device__ __align__(16) __nv_bfloat16 g_w_lo[CH * CH];
// fragment-permuted qkv weights: [head][j(24)][kstep(8)][lane(32)] uint2
__device__ __align__(16) uint2 g_qwB_hi[NHEADS * 24 * 8 * 32];
__device__ __align__(16) uint2 g_qwB_lo[NHEADS * 24 * 8 * 32];

// ==================== mma helpers ====================
__device__ __forceinline__ unsigned s2u(const void* p) {
    return (unsigned)__cvta_generic_to_shared(p);
}
__device__ __forceinline__ void ldsm_x4(unsigned* r, unsigned addr) {
    asm volatile("ldmatrix.sync.aligned.m8n8.x4.shared.b16 {%0,%1,%2,%3}, [%4];"
        : "=r"(r[0]), "=r"(r[1]), "=r"(r[2]), "=r"(r[3]) : "r"(addr));
}
__device__ __forceinline__ void mma16816(float* c, const unsigned* a, const unsigned* b) {
    asm volatile("mma.sync.aligned.m16n8k16.row.col.f32.bf16.bf16.f32 "
        "{%0,%1,%2,%3}, {%4,%5,%6,%7}, {%8,%9}, {%0,%1,%2,%3};"
        : "+f"(c[0]), "+f"(c[1]), "+f"(c[2]), "+f"(c[3])
        : "r"(a[0]), "r"(a[1]), "r"(a[2]), "r"(a[3]), "r"(b[0]), "r"(b[1]));
}
__device__ __forceinline__ unsigned packbf2(float a, float b) {
    __nv_bfloat162 p = __halves2bfloat162(__float2bfloat16(a), __float2bfloat16(b));
    return *reinterpret_cast<unsigned*>(&p);
}

// ==================== prep kernels ====================
__global__ void wsplit_kernel(const float* __restrict__ w) {
    int i = blockIdx.x * 256 + threadIdx.x;
    float v = w[i];
    __nv_bfloat16 h = __float2bfloat16(v);
    g_w_hi[i] = h;
    g_w_lo[i] = __float2bfloat16(v - __bfloat162float(h));
}

__global__ void qkvsplit_kernel(const float* __restrict__ w) {
    int i = blockIdx.x * 256 + threadIdx.x;      // 4*192*64 = 49152
    int h = i / (192 * 64);
    int rem = i % (192 * 64);
    int n = rem / 64;
    int p = rem % 64;
    float v0 = w[((size_t)h * 192 + n) * 128 + p * 2];
    float v1 = w[((size_t)h * 192 + n) * 128 + p * 2 + 1];
    __nv_bfloat16 h0 = __float2bfloat16(v0), h1 = __float2bfloat16(v1);
    float l0 = v0 - __bfloat162float(h0), l1 = v1 - __bfloat162float(h1);
    unsigned hi = (unsigned)__bfloat16_as_ushort(h0) |
                  ((unsigned)__bfloat16_as_ushort(h1) << 16);
    unsigned lo = (unsigned)__bfloat16_as_ushort(__float2bfloat16(l0)) |
                  ((unsigned)__bfloat16_as_ushort(__float2bfloat16(l1)) << 16);
    int j = n >> 3, kstep = p >> 3, q = p & 7;
    int r = q >> 2, lm4 = q & 3;
    int lane = (n & 7) * 4 + lm4;
    int base = ((h * 24 + j) * 8 + kstep) * 32 + lane;
    reinterpret_cast<unsigned*>(g_qwB_hi)[base * 2 + r] = hi;
    reinterpret_cast<unsigned*>(g_qwB_lo)[base * 2 + r] = lo;
}

// ==================== Phase A: cascaded heads ====================

struct __align__(16) SmemA {
    __nv_bfloat16 ah[64 * ARS];   // feat hi (rows 49-63 zero)
    __nv_bfloat16 al[64 * ARS];   // feat lo
    float y[NTOK * YST];
    float q[NTOK * KDIM];
    float attn[2452];
    float dww[25 * 32];
    float qscale[QO];
    float qbias[QO];
    float dws[KDIM], dwb[KDIM];
    float ab[NHEADS * NTOK];
    unsigned char bidx[NTOK * NTOK];
};

__global__ void __launch_bounds__(256, 2) cascade_kernel(
    const float* __restrict__ x,
    const float* __restrict__ qkv_g,  const float* __restrict__ qkv_b,
    const float* __restrict__ qkv_m,  const float* __restrict__ qkv_v,
    const float* __restrict__ dw_w,   const float* __restrict__ dw_g,
    const float* __restrict__ dw_b,   const float* __restrict__ dw_m,
    const float* __restrict__ dw_v,   const float* __restrict__ attn_bias,
    const int* __restrict__ bias_idxs)
{
    extern __shared__ unsigned char smem_raw[];
    SmemA& s = *reinterpret_cast<SmemA*>(smem_raw);
    const int t    = threadIdx.x;
    const int b    = blockIdx.x;
    const int lane = t & 31;
    const int warp = t >> 5;
    const float scale = rsqrtf((float)KDIM);
    const size_t xoff = (size_t)b * NTOK * CH;

    for (int j = t; j < NTOK * NTOK; j += 256) s.bidx[j] = (unsigned char)bias_idxs[j];
    for (int j = t; j < NHEADS * NTOK; j += 256) s.ab[j] = attn_bias[j];
    // zero pad rows 49..63 of A buffers
    for (int j = t; j < 15 * ARS; j += 256) {
        s.ah[49 * ARS + j] = __float2bfloat16(0.f);
        s.al[49 * ARS + j] = __float2bfloat16(0.f);
    }

    const int a_r = lane & 15, a_c = (lane >> 4) * 8;

    for (int head = 0; head < NHEADS; ++head) {
        // ---- feat update + bf16 hi/lo split ----
        for (int jdx = t; jdx < NTOK * 128; jdx += 256) {
            int n = jdx >> 7, d = jdx & 127;
            float v;
            if (head == 0) {
                v = x[xoff + n * CH + d];
            } else {
                v = __bfloat162float(s.ah[n * ARS + d]) +
                    __bfloat162float(s.al[n * ARS + d]) +
                    x[xoff + n * CH + head * 128 + d];
            }
            __nv_bfloat16 hv = __float2bfloat16(v);
            s.ah[n * ARS + d] = hv;
            s.al[n * ARS + d] = __float2bfloat16(v - __bfloat162float(hv));
        }
        // ---- BN folds ----
        if (t < QO) {
            float sc = qkv_g[head * QO + t] * rsqrtf(qkv_v[head * QO + t] + EPS);
            s.qscale[t] = sc;
            s.qbias[t]  = qkv_b[head * QO + t] - qkv_m[head * QO + t] * sc;
        } else if (t < QO + KDIM) {
            int c = t - QO;
            float sc = dw_g[head * KDIM + c] * rsqrtf(dw_v[head * KDIM + c] + EPS);
            s.dws[c] = sc;
            s.dwb[c] = dw_b[head * KDIM + c] - dw_m[head * KDIM + c] * sc;
        }
        for (int j = t; j < KDIM * 25; j += 256) {
            int c = j / 25, tap = j % 25;
            s.dww[tap * 32 + c] = dw_w[(head * KDIM + c) * 25 + tap];
        }
        __syncthreads();

        // ---- qkv GEMM via bf16 mma (3-term split) ----
        {
            float qacc[4][3][4];
            #pragma unroll
            for (int m = 0; m < 4; ++m)
                #pragma unroll
                for (int j = 0; j < 3; ++j)
                    #pragma unroll
                    for (int q = 0; q < 4; ++q) qacc[m][j][q] = 0.f;

            for (int k = 0; k < 8; ++k) {
                uint2 bh[3], bl[3];
                #pragma unroll
                for (int j = 0; j < 3; ++j) {
                    int bi = ((head * 24 + warp * 3 + j) * 8 + k) * 32 + lane;
                    bh[j] = g_qwB_hi[bi];
                    bl[j] = g_qwB_lo[bi];
                }
                #pragma unroll
                for (int m = 0; m < 4; ++m) {
                    unsigned Ah[4], Al[4];
                    ldsm_x4(Ah, s2u(&s.ah[(m * 16 + a_r) * ARS + k * 16 + a_c]));
                    ldsm_x4(Al, s2u(&s.al[(m * 16 + a_r) * ARS + k * 16 + a_c]));
                    #pragma unroll
                    for (int j = 0; j < 3; ++j) {
                        mma16816(qacc[m][j], Ah, reinterpret_cast<const unsigned*>(&bh[j]));
                        mma16816(qacc[m][j], Ah, reinterpret_cast<const unsigned*>(&bl[j]));
                        mma16816(qacc[m][j], Al, reinterpret_cast<const unsigned*>(&bh[j]));
                    }
                }
            }
            // epilogue: BN fold -> y fp32
            #pragma unroll
            for (int m = 0; m < 4; ++m) {
                int r0 = m * 16 + (lane >> 2);
                #pragma unroll
                for (int j = 0; j < 3; ++j) {
                    int c0 = warp * 24 + j * 8 + (lane & 3) * 2;
                    float s0 = s.qscale[c0], s1 = s.qscale[c0 + 1];
                    float b0 = s.qbias[c0], b1 = s.qbias[c0 + 1];
                    if (r0 < NTOK)
                        *reinterpret_cast<float2*>(&s.y[r0 * YST + c0]) =
                            make_float2(qacc[m][j][0] * s0 + b0, qacc[m][j][1] * s1 + b1);
                    if (r0 + 8 < NTOK)
                        *reinterpret_cast<float2*>(&s.y[(r0 + 8) * YST + c0]) =
                            make_float2(qacc[m][j][2] * s0 + b0, qacc[m][j][3] * s1 + b1);
                }
            }
        }
        __syncthreads();

        // ---- depthwise 5x5 conv (+BN) ----
        for (int idx = t; idx < NTOK * KDIM; idx += 256) {
            int n = idx >> 5, c = idx & 31;
            int r = n / 7, sc_ = n % 7;
            float sum = 0.f;
            #pragma unroll
            for (int a = 0; a < 5; ++a) {
                int rr = r + a - 2;
                if ((unsigned)rr < 7u) {
                    #pragma unroll
                    for (int bb = 0; bb < 5; ++bb) {
                        int ss = sc_ + bb - 2;
                        if ((unsigned)ss < 7u)
                            sum += s.y[(rr * 7 + ss) * YST + c] * s.dww[(a * 5 + bb) * 32 + c];
                    }
                }
            }
            s.q[n * 32 + c] = sum * s.dws[c] + s.dwb[c];
        }
        __syncthreads();

        // ---- scores + bias ----
        for (int p = t; p < NTOK * NTOK; p += 256) {
            int n = p / 49, m = p % 49;
            const float4* qp = reinterpret_cast<const float4*>(&s.q[n * 32]);
            const float4* kp = reinterpret_cast<const float4*>(&s.y[m * YST + KDIM]);
            float sum = 0.f;
            #pragma unroll
            for (int k4 = 0; k4 < 8; ++k4) {
                float4 a = qp[k4], bb = kp[k4];
                sum += a.x * bb.x + a.y * bb.y + a.z * bb.z + a.w * bb.w;
            }
            s.attn[p] = sum * scale + s.ab[head * NTOK + s.bidx[p]];
        }
        __syncthreads();

        // ---- softmax ----
        for (int r = warp; r < NTOK; r += 8) {
            float a = s.attn[r * 49 + lane];
            bool hasb = (lane + 32) < 49;
            float bv = hasb ? s.attn[r * 49 + lane + 32] : -1e30f;
            float mx = fmaxf(a, bv);
            #pragma unroll
            for (int off = 16; off > 0; off >>= 1)
                mx = fmaxf(mx, __shfl_xor_sync(0xffffffffu, mx, off));
            float ea = __expf(a - mx);
            float eb = hasb ? __expf(bv - mx) : 0.f;
            float sm = ea + eb;
            #pragma unroll
            for (int off = 16; off > 0; off >>= 1)
                sm += __shfl_xor_sync(0xffffffffu, sm, off);
            float inv = __frcp_rn(sm);
            s.attn[r * 49 + lane] = ea * inv;
            if (hasb) s.attn[r * 49 + lane + 32] = eb * inv;
        }
        __syncthreads();

        // ---- feat_new = attn @ v ----
        float fac[4][8];
        #pragma unroll
        for (int j = 0; j < 4; ++j)
            #pragma unroll
            for (int q = 0; q < 8; ++q) fac[j][q] = 0.f;

        #pragma unroll
        for (int j = 0; j < 4; ++j) {
            int tile = t + j * 256;
            if (tile < 800) {
                int nt = tile / 32, dt = tile % 32;
                int n0 = nt * 2, d0 = dt * 4;
                #pragma unroll 7
                for (int m = 0; m < NTOK; ++m) {
                    float a0 = s.attn[n0 * 49 + m];
                    float a1 = s.attn[n0 * 49 + 49 + m];
                    float4 v4 = *reinterpret_cast<const float4*>(&s.y[m * YST + 64 + d0]);
                    fac[j][0] += a0 * v4.x; fac[j][1] += a0 * v4.y;
                    fac[j][2] += a0 * v4.z; fac[j][3] += a0 * v4.w;
                    fac[j][4] += a1 * v4.x; fac[j][5] += a1 * v4.y;
                    fac[j][6] += a1 * v4.z; fac[j][7] += a1 * v4.w;
                }
            }
        }
        __syncthreads();
        #pragma unroll
        for (int j = 0; j < 4; ++j) {
            int tile = t + j * 256;
            if (tile < 800) {
                int nt = tile / 32, dt = tile % 32;
                int n0 = nt * 2, d0 = dt * 4;
                #pragma unroll
                for (int half = 0; half < 2; ++half) {
                    int n = n0 + half;
                    if (n < NTOK) {
                        float v0 = fac[j][half * 4 + 0], v1 = fac[j][half * 4 + 1];
                        float v2 = fac[j][half * 4 + 2], v3 = fac[j][half * 4 + 3];
                        // split into ah/al (feat for next head)
                        __nv_bfloat16 h0 = __float2bfloat16(v0), h1 = __float2bfloat16(v1);
                        __nv_bfloat16 h2 = __float2bfloat16(v2), h3 = __float2bfloat16(v3);
                        unsigned hp0 = (unsigned)__bfloat16_as_ushort(h0) |
                                       ((unsigned)__bfloat16_as_ushort(h1) << 16);
                        unsigned hp1 = (unsigned)__bfloat16_as_ushort(h2) |
                                       ((unsigned)__bfloat16_as_ushort(h3) << 16);
                        unsigned lp0 = packbf2(v0 - __bfloat162float(h0), v1 - __bfloat162float(h1));
                        unsigned lp1 = packbf2(v2 - __bfloat162float(h2), v3 - __bfloat162float(h3));
                        *reinterpret_cast<unsigned*>(&s.ah[n * ARS + d0]) = hp0;
                        *reinterpret_cast<unsigned*>(&s.ah[n * ARS + d0 + 2]) = hp1;
                        *reinterpret_cast<unsigned*>(&s.al[n * ARS + d0]) = lp0;
                        *reinterpret_cast<unsigned*>(&s.al[n * ARS + d0 + 2]) = lp1;
                        // relu -> g_h hi/lo
                        float r0 = fmaxf(v0, 0.f), r1 = fmaxf(v1, 0.f);
                        float r2 = fmaxf(v2, 0.f), r3 = fmaxf(v3, 0.f);
                        __nv_bfloat16 g0 = __float2bfloat16(r0), g1 = __float2bfloat16(r1);
                        __nv_bfloat16 g2 = __float2bfloat16(r2), g3 = __float2bfloat16(r3);
                        uint2 uh, ul;
                        uh.x = (unsigned)__bfloat16_as_ushort(g0) |
                               ((unsigned)__bfloat16_as_ushort(g1) << 16);
                        uh.y = (unsigned)__bfloat16_as_ushort(g2) |
                               ((unsigned)__bfloat16_as_ushort(g3) << 16);
                        ul.x = packbf2(r0 - __bfloat162float(g0), r1 - __bfloat162float(g1));
                        ul.y = packbf2(r2 - __bfloat162float(g2), r3 - __bfloat162float(g3));
                        size_t off = ((size_t)b * NTOK + n) * CH + head * 128 + d0;
                        *reinterpret_cast<uint2*>(&g_h_hi[off]) = uh;
                        *reinterpret_cast<uint2*>(&g_h_lo[off]) = ul;
                    }
                }
            }
        }
        __syncthreads();
    }
}

// ==================== Phase B: projection via bf16 mma ====================

#define PM 128
#define PN 64
#define PKC 32
#define AS 40

__global__ void __launch_bounds__(256, 2) proj_mma_kernel(
    const float* __restrict__ proj_g, const float* __restrict__ proj_b,
    const float* __restrict__ proj_m, const float* __restrict__ proj_v,
    float* __restrict__ out)
{
    __shared__ __align__(16) __nv_bfloat16 sAh[PM * AS];
    __shared__ __align__(16) __nv_bfloat16 sAl[PM * AS];
    __shared__ __align__(16) __nv_bfloat16 sBh[PN * AS];
    __shared__ __align__(16) __nv_bfloat16 sBl[PN * AS];
    __shared__ float sPs[PN], sPb[PN];

    const int t = threadIdx.x, lane = t & 31, warp = t >> 5;
    const int row0 = blockIdx.y * PM, col0 = blockIdx.x * PN;

    if (t < PN) {
        int o = col0 + t;
        float sc = proj_g[o] * rsqrtf(proj_v[o] + EPS);
        sPs[t] = sc;
        sPb[t] = proj_b[o] - proj_m[o] * sc;
    }

    const int ar0 = t >> 2;
    const int akk = (t & 3) * 8;

    float acc[2][4][4];
    #pragma unroll
    for (int mt = 0; mt < 2; ++mt)
        #pragma unroll
        for (int nt = 0; nt < 4; ++nt)
            #pragma unroll
            for (int q = 0; q < 4; ++q) acc[mt][nt][q] = 0.f;

    const int wm = (warp >> 1) * 32, wn = (warp & 1) * 32;
    const int a_r = lane & 15, a_c = (lane >> 4) * 8;
    const int b_r = (lane & 7) + ((lane & 16) ? 8 : 0);
    const int b_c = (lane & 8) ? 8 : 0;

    uint4 rah0, rah1, ral0, ral1, rbh, rbl;
    {
        size_t base  = (size_t)(row0 + ar0) * 512 + akk;
        rah0 = *reinterpret_cast<const uint4*>(&g_h_hi[base]);
        ral0 = *reinterpret_cast<const uint4*>(&g_h_lo[base]);
        rah1 = *reinterpret_cast<const uint4*>(&g_h_hi[base + (size_t)64 * 512]);
        ral1 = *reinterpret_cast<const uint4*>(&g_h_lo[base + (size_t)64 * 512]);
        size_t bb = (size_t)(col0 + ar0) * 512 + akk;
        rbh = *reinterpret_cast<const uint4*>(&g_w_hi[bb]);
        rbl = *reinterpret_cast<const uint4*>(&g_w_lo[bb]);
    }

    for (int kc = 0; kc < 16; ++kc) {
        __syncthreads();
        *reinterpret_cast<uint4*>(&sAh[ar0 * AS + akk]) = rah0;
        *reinterpret_cast<uint4*>(&sAl[ar0 * AS + akk]) = ral0;
        *reinterpret_cast<uint4*>(&sAh[(ar0 + 64) * AS + akk]) = rah1;
        *reinterpret_cast<uint4*>(&sAl[(ar0 + 64) * AS + akk]) = ral1;
        *reinterpret_cast<uint4*>(&sBh[ar0 * AS + akk]) = rbh;
        *reinterpret_cast<uint4*>(&sBl[ar0 * AS + akk]) = rbl;
        __syncthreads();
        if (kc < 15) {
            size_t base = (size_t)(row0 + ar0) * 512 + (kc + 1) * PKC + akk;
            rah0 = *reinterpret_cast<const uint4*>(&g_h_hi[base]);
            ral0 = *reinterpret_cast<const uint4*>(&g_h_lo[base]);
            rah1 = *reinterpret_cast<const uint4*>(&g_h_hi[base + (size_t)64 * 512]);
            ral1 = *reinterpret_cast<const uint4*>(&g_h_lo[base + (size_t)64 * 512]);
            size_t bb = (size_t)(col0 + ar0) * 512 + (kc + 1) * PKC + akk;
            rbh = *reinterpret_cast<const uint4*>(&g_w_hi[bb]);
            rbl = *reinterpret_cast<const uint4*>(&g_w_lo[bb]);
        }
        #pragma unroll
        for (int k16 = 0; k16 < 2; ++k16) {
            int kb = k16 * 16;
            unsigned Ah[2][4], Al[2][4], Bh[2][4], Bl[2][4];
            #pragma unroll
            for (int mt = 0; mt < 2; ++mt) {
                ldsm_x4(Ah[mt], s2u(&sAh[(wm + mt * 16 + a_r) * AS + kb + a_c]));
                ldsm_x4(Al[mt], s2u(&sAl[(wm + mt * 16 + a_r) * AS + kb + a_c]));
            }
            #pragma unroll
            for (int g = 0; g < 2; ++g) {
                int br = wn + g * 16 + b_r;
                ldsm_x4(Bh[g], s2u(&sBh[br * AS + kb + b_c]));
                ldsm_x4(Bl[g], s2u(&sBl[br * AS + kb + b_c]));
            }
            #pragma unroll
            for (int mt = 0; mt < 2; ++mt)
                #pragma unroll
                for (int nt = 0; nt < 4; ++nt) {
                    const unsigned* bh = &Bh[nt >> 1][(nt & 1) * 2];
                    const unsigned* bl = &Bl[nt >> 1][(nt & 1) * 2];
                    mma16816(acc[mt][nt], Ah[mt], bh);
                    mma16816(acc[mt][nt], Ah[mt], bl);
                    mma16816(acc[mt][nt], Al[mt], bh);
                }
        }
    }

    const int er = lane >> 2, ec = (lane & 3) * 2;
    #pragma unroll
    for (int mt = 0; mt < 2; ++mt)
        #pragma unroll
        for (int nt = 0; nt < 4; ++nt) {
            int cl = wn + nt * 8 + ec;
            float s0 = sPs[cl], s1 = sPs[cl + 1];
            float b0 = sPb[cl], b1 = sPb[cl + 1];
            size_t gr = (size_t)(row0 + wm + mt * 16 + er) * 512 + col0 + cl;
            *reinterpret_cast<float2*>(&out[gr]) =
                make_float2(acc[mt][nt][0] * s0 + b0, acc[mt][nt][1] * s1 + b1);
            *reinterpret_cast<float2*>(&out[gr + (size_t)8 * 512]) =
                make_float2(acc[mt][nt][2] * s0 + b0, acc[mt][nt][3] * s1 + b1);
        }
}

// ==================== launch ====================

extern "C" void kernel_launch(void* const* d_in, const int* in_sizes, int n_in,
                              void* d_out, int out_size) {
    const float* x         = (const float*)d_in[0];
    const float* qkv_w     = (const float*)d_in[1];
    const float* qkv_g     = (const float*)d_in[2];
    const float* qkv_b     = (const float*)d_in[3];
    const float* qkv_m     = (const float*)d_in[4];
    const float* qkv_v     = (const float*)d_in[5];
    const float* dw_w      = (const float*)d_in[6];
    const float* dw_g      = (const float*)d_in[7];
    const float* dw_b      = (const float*)d_in[8];
    const float* dw_m      = (const float*)d_in[9];
    const float* dw_v      = (const float*)d_in[10];
    const float* proj_w    = (const float*)d_in[11];
    const float* proj_g    = (const float*)d_in[12];
    const float* proj_b    = (const float*)d_in[13];
    const float* proj_m    = (const float*)d_in[14];
    const float* proj_v    = (const float*)d_in[15];
    const float* attn_bias = (const float*)d_in[16];
    const int*   bias_idxs = (const int*)d_in[17];
    float* out = (float*)d_out;

    cudaFuncSetAttribute(cascade_kernel,
                         cudaFuncAttributeMaxDynamicSharedMemorySize,
                         (int)sizeof(SmemA));

    wsplit_kernel<<<1024, 256>>>(proj_w);
    qkvsplit_kernel<<<192, 256>>>(qkv_w);

    cascade_kernel<<<BATCH, 256, sizeof(SmemA)>>>(
        x, qkv_g, qkv_b, qkv_m, qkv_v,
        dw_w, dw_g, dw_b, dw_m, dw_v, attn_bias, bias_idxs);

    proj_mma_kernel<<<dim3(8, 784), 256>>>(proj_g, proj_b, proj_m, proj_v, out);
}

// round 4
// speedup vs baseline: 3.9507x; 1.2095x over previous
#include <cuda_runtime.h>
#include <cuda_bf16.h>

#define BATCH   2048
#define NTOK    49
#define CH      512
#define NHEADS  4
#define KDIM    32
#define DV      128
#define QO      192
#define EPS     1e-5f
#define FST     136      // feat / v row stride (bf16)
#define KQS     40       // k / q row stride (bf16)
#define ATS     72       // attn-prob row stride (bf16)
#define ASF     52       // attn fp32 score row stride
#define YQS     36       // conv-input fp32 stride

// -------- global scratch --------
__device__ __align__(16) __nv_bfloat16 g_h_hi[(size_t)BATCH * NTOK * CH];
__device__ __align__(16) __nv_bfloat16 g_h_lo[(size_t)BATCH * NTOK * CH];
// proj weights, B-fragment permuted: [n8(64)][k16(32)][lane(32)] uint2
__device__ __align__(16) uint2 g_wB_hi[64 * 32 * 32];
__device__ __align__(16) uint2 g_wB_lo[64 * 32 * 32];
// qkv weights, B-fragment permuted: [head][j(24)][kstep(8)][lane(32)] uint2
__device__ __align__(16) uint2 g_qwB_hi[NHEADS * 24 * 8 * 32];
__device__ __align__(16) uint2 g_qwB_lo[NHEADS * 24 * 8 * 32];

// ==================== mma helpers ====================
__device__ __forceinline__ unsigned s2u(const void* p) {
    return (unsigned)__cvta_generic_to_shared(p);
}
__device__ __forceinline__ void ldsm_x4(unsigned* r, unsigned addr) {
    asm volatile("ldmatrix.sync.aligned.m8n8.x4.shared.b16 {%0,%1,%2,%3}, [%4];"
        : "=r"(r[0]), "=r"(r[1]), "=r"(r[2]), "=r"(r[3]) : "r"(addr));
}
__device__ __forceinline__ void ldsm_x4_t(unsigned* r, unsigned addr) {
    asm volatile("ldmatrix.sync.aligned.m8n8.x4.trans.shared.b16 {%0,%1,%2,%3}, [%4];"
        : "=r"(r[0]), "=r"(r[1]), "=r"(r[2]), "=r"(r[3]) : "r"(addr));
}
__device__ __forceinline__ void mma16816(float* c, const unsigned* a, const unsigned* b) {
    asm volatile("mma.sync.aligned.m16n8k16.row.col.f32.bf16.bf16.f32 "
        "{%0,%1,%2,%3}, {%4,%5,%6,%7}, {%8,%9}, {%0,%1,%2,%3};"
        : "+f"(c[0]), "+f"(c[1]), "+f"(c[2]), "+f"(c[3])
        : "r"(a[0]), "r"(a[1]), "r"(a[2]), "r"(a[3]), "r"(b[0]), "r"(b[1]));
}
__device__ __forceinline__ unsigned packbf2(float a, float b) {
    __nv_bfloat162 p = __halves2bfloat162(__float2bfloat16(a), __float2bfloat16(b));
    return *reinterpret_cast<unsigned*>(&p);
}
// split 2 floats into packed hi + packed lo bf16x2
__device__ __forceinline__ void split2(float v0, float v1, unsigned& hp, unsigned& lp) {
    __nv_bfloat16 h0 = __float2bfloat16(v0), h1 = __float2bfloat16(v1);
    hp = (unsigned)__bfloat16_as_ushort(h0) | ((unsigned)__bfloat16_as_ushort(h1) << 16);
    lp = packbf2(v0 - __bfloat162float(h0), v1 - __bfloat162float(h1));
}

// ==================== prep kernels ====================
__global__ void wsplit_kernel(const float* __restrict__ w) {
    int i = blockIdx.x * 256 + threadIdx.x;       // 65536
    int j0 = i >> 10;          // n8 tile
    int s_ = (i >> 5) & 31;    // k16 step
    int l  = i & 31;
    int n  = j0 * 8 + (l >> 2);
    int k0 = s_ * 16 + (l & 3) * 2;
    float a0 = w[n * 512 + k0],     a1 = w[n * 512 + k0 + 1];
    float a2 = w[n * 512 + k0 + 8], a3 = w[n * 512 + k0 + 9];
    uint2 hi, lo;
    split2(a0, a1, hi.x, lo.x);
    split2(a2, a3, hi.y, lo.y);
    g_wB_hi[i] = hi;
    g_wB_lo[i] = lo;
}

__global__ void qkvsplit_kernel(const float* __restrict__ w) {
    int i = blockIdx.x * 256 + threadIdx.x;       // 4*192*64 = 49152
    int h = i / (192 * 64);
    int rem = i % (192 * 64);
    int n = rem / 64;
    int p = rem % 64;
    float v0 = w[((size_t)h * 192 + n) * 128 + p * 2];
    float v1 = w[((size_t)h * 192 + n) * 128 + p * 2 + 1];
    unsigned hi, lo;
    split2(v0, v1, hi, lo);
    int j = n >> 3, kstep = p >> 3, q = p & 7;
    int r = q >> 2, lm4 = q & 3;
    int lane = (n & 7) * 4 + lm4;
    int base = ((h * 24 + j) * 8 + kstep) * 32 + lane;
    reinterpret_cast<unsigned*>(g_qwB_hi)[base * 2 + r] = hi;
    reinterpret_cast<unsigned*>(g_qwB_lo)[base * 2 + r] = lo;
}

// ==================== Phase A: cascaded heads (all-mma) ====================

struct __align__(16) SmemA {
    __nv_bfloat16 ah[64 * FST], al[64 * FST];   // feat hi/lo
    __nv_bfloat16 vh[64 * FST], vl[64 * FST];   // v hi/lo [m][d]
    union U1 {
        struct { __nv_bfloat16 kh[64 * KQS], kl[64 * KQS],
                               qh[64 * KQS], ql[64 * KQS]; } s1;
        struct { __nv_bfloat16 ath[64 * ATS], atl[64 * ATS]; } s2;
    } u1;
    union U2 { float attn[49 * ASF]; float yq[49 * YQS]; } u2;
    float dww[25 * 32];
    float qscale[QO], qbias[QO];
    float dws[KDIM], dwb[KDIM];
    float ab[NHEADS * NTOK];
    unsigned char bidx[NTOK * NTOK];
};

__global__ void __launch_bounds__(256, 2) cascade_kernel(
    const float* __restrict__ x,
    const float* __restrict__ qkv_g,  const float* __restrict__ qkv_b,
    const float* __restrict__ qkv_m,  const float* __restrict__ qkv_v,
    const float* __restrict__ dw_w,   const float* __restrict__ dw_g,
    const float* __restrict__ dw_b,   const float* __restrict__ dw_m,
    const float* __restrict__ dw_v,   const float* __restrict__ attn_bias,
    const int* __restrict__ bias_idxs)
{
    extern __shared__ unsigned char smem_raw[];
    SmemA& s = *reinterpret_cast<SmemA*>(smem_raw);
    const int t    = threadIdx.x;
    const int b    = blockIdx.x;
    const int lane = t & 31;
    const int warp = t >> 5;
    const float scale = rsqrtf((float)KDIM);
    const size_t xoff = (size_t)b * NTOK * CH;

    for (int j = t; j < NTOK * NTOK; j += 256) s.bidx[j] = (unsigned char)bias_idxs[j];
    for (int j = t; j < NHEADS * NTOK; j += 256) s.ab[j] = attn_bias[j];
    // zero pad rows 49..63 of feat + v buffers
    for (int j = t; j < 15 * FST; j += 256) {
        __nv_bfloat16 z = __float2bfloat16(0.f);
        s.ah[49 * FST + j] = z; s.al[49 * FST + j] = z;
        s.vh[49 * FST + j] = z; s.vl[49 * FST + j] = z;
    }

    const int a_r = lane & 15, a_c = (lane >> 4) * 8;
    const int b_r = (lane & 7) + ((lane & 16) ? 8 : 0);
    const int b_c = (lane & 8) ? 8 : 0;

    for (int head = 0; head < NHEADS; ++head) {
        // ---- feat update + hi/lo split ----
        for (int jdx = t; jdx < NTOK * 128; jdx += 256) {
            int n = jdx >> 7, d = jdx & 127;
            float v;
            if (head == 0) {
                v = x[xoff + n * CH + d];
            } else {
                v = __bfloat162float(s.ah[n * FST + d]) +
                    __bfloat162float(s.al[n * FST + d]) +
                    x[xoff + n * CH + head * 128 + d];
            }
            __nv_bfloat16 hv = __float2bfloat16(v);
            s.ah[n * FST + d] = hv;
            s.al[n * FST + d] = __float2bfloat16(v - __bfloat162float(hv));
        }
        // ---- BN folds ----
        if (t < QO) {
            float sc = qkv_g[head * QO + t] * rsqrtf(qkv_v[head * QO + t] + EPS);
            s.qscale[t] = sc;
            s.qbias[t]  = qkv_b[head * QO + t] - qkv_m[head * QO + t] * sc;
        } else if (t < QO + KDIM) {
            int c = t - QO;
            float sc = dw_g[head * KDIM + c] * rsqrtf(dw_v[head * KDIM + c] + EPS);
            s.dws[c] = sc;
            s.dwb[c] = dw_b[head * KDIM + c] - dw_m[head * KDIM + c] * sc;
        }
        for (int j = t; j < KDIM * 25; j += 256) {
            int c = j / 25, tap = j % 25;
            s.dww[tap * 32 + c] = dw_w[(head * KDIM + c) * 25 + tap];
        }
        __syncthreads();

        // ================= qkv GEMM (mma, 3-term) =================
        {
            float qacc[4][3][4];
            #pragma unroll
            for (int m = 0; m < 4; ++m)
                #pragma unroll
                for (int j = 0; j < 3; ++j)
                    #pragma unroll
                    for (int q = 0; q < 4; ++q) qacc[m][j][q] = 0.f;

            for (int k = 0; k < 8; ++k) {
                uint2 bh[3], bl[3];
                #pragma unroll
                for (int j = 0; j < 3; ++j) {
                    int bi = ((head * 24 + warp * 3 + j) * 8 + k) * 32 + lane;
                    bh[j] = g_qwB_hi[bi];
                    bl[j] = g_qwB_lo[bi];
                }
                #pragma unroll
                for (int m = 0; m < 4; ++m) {
                    unsigned Ah[4], Al[4];
                    ldsm_x4(Ah, s2u(&s.ah[(m * 16 + a_r) * FST + k * 16 + a_c]));
                    ldsm_x4(Al, s2u(&s.al[(m * 16 + a_r) * FST + k * 16 + a_c]));
                    #pragma unroll
                    for (int j = 0; j < 3; ++j) {
                        mma16816(qacc[m][j], Ah, reinterpret_cast<const unsigned*>(&bh[j]));
                        mma16816(qacc[m][j], Ah, reinterpret_cast<const unsigned*>(&bl[j]));
                        mma16816(qacc[m][j], Al, reinterpret_cast<const unsigned*>(&bh[j]));
                    }
                }
            }
            // epilogue: BN fold -> yq (q fp32) | kh/kl | vh/vl
            #pragma unroll
            for (int m = 0; m < 4; ++m) {
                int rb = m * 16 + (lane >> 2);
                #pragma unroll
                for (int j = 0; j < 3; ++j) {
                    int c0 = warp * 24 + j * 8 + (lane & 3) * 2;
                    float sc0 = s.qscale[c0], sc1 = s.qscale[c0 + 1];
                    float bb0 = s.qbias[c0],  bb1 = s.qbias[c0 + 1];
                    #pragma unroll
                    for (int h2 = 0; h2 < 2; ++h2) {
                        int r = rb + h2 * 8;
                        if (r < NTOK) {
                            float y0 = qacc[m][j][h2 * 2 + 0] * sc0 + bb0;
                            float y1 = qacc[m][j][h2 * 2 + 1] * sc1 + bb1;
                            if (c0 < 32) {
                                s.u2.yq[r * YQS + c0]     = y0;
                                s.u2.yq[r * YQS + c0 + 1] = y1;
                            } else if (c0 < 64) {
                                unsigned hp, lp;
                                split2(y0, y1, hp, lp);
                                *reinterpret_cast<unsigned*>(&s.u1.s1.kh[r * KQS + c0 - 32]) = hp;
                                *reinterpret_cast<unsigned*>(&s.u1.s1.kl[r * KQS + c0 - 32]) = lp;
                            } else {
                                unsigned hp, lp;
                                split2(y0, y1, hp, lp);
                                *reinterpret_cast<unsigned*>(&s.vh[r * FST + c0 - 64]) = hp;
                                *reinterpret_cast<unsigned*>(&s.vl[r * FST + c0 - 64]) = lp;
                            }
                        }
                    }
                }
            }
        }
        __syncthreads();

        // ================= depthwise 5x5 conv (+BN) -> qh/ql =================
        for (int idx = t; idx < NTOK * KDIM; idx += 256) {
            int n = idx >> 5, c = idx & 31;
            int r = n / 7, sc_ = n % 7;
            float sum = 0.f;
            #pragma unroll
            for (int a = 0; a < 5; ++a) {
                int rr = r + a - 2;
                if ((unsigned)rr < 7u) {
                    #pragma unroll
                    for (int bb = 0; bb < 5; ++bb) {
                        int ss = sc_ + bb - 2;
                        if ((unsigned)ss < 7u)
                            sum += s.u2.yq[(rr * 7 + ss) * YQS + c] * s.dww[(a * 5 + bb) * 32 + c];
                    }
                }
            }
            float qv = sum * s.dws[c] + s.dwb[c];
            __nv_bfloat16 hv = __float2bfloat16(qv);
            s.u1.s1.qh[n * KQS + c] = hv;
            s.u1.s1.ql[n * KQS + c] = __float2bfloat16(qv - __bfloat162float(hv));
        }
        __syncthreads();

        // ================= qk scores (mma, 3-term) =================
        {
            const int wm = (warp & 3) * 16, wn = (warp >> 2) * 32;
            float sacc[4][4];
            #pragma unroll
            for (int nt = 0; nt < 4; ++nt)
                #pragma unroll
                for (int q = 0; q < 4; ++q) sacc[nt][q] = 0.f;

            #pragma unroll
            for (int k16 = 0; k16 < 2; ++k16) {
                unsigned Ah[4], Al[4];
                ldsm_x4(Ah, s2u(&s.u1.s1.qh[(wm + a_r) * KQS + k16 * 16 + a_c]));
                ldsm_x4(Al, s2u(&s.u1.s1.ql[(wm + a_r) * KQS + k16 * 16 + a_c]));
                unsigned Bh[2][4], Bl[2][4];
                #pragma unroll
                for (int g = 0; g < 2; ++g) {
                    ldsm_x4(Bh[g], s2u(&s.u1.s1.kh[(wn + g * 16 + b_r) * KQS + k16 * 16 + b_c]));
                    ldsm_x4(Bl[g], s2u(&s.u1.s1.kl[(wn + g * 16 + b_r) * KQS + k16 * 16 + b_c]));
                }
                #pragma unroll
                for (int nt = 0; nt < 4; ++nt) {
                    const unsigned* bh = &Bh[nt >> 1][(nt & 1) * 2];
                    const unsigned* bl = &Bl[nt >> 1][(nt & 1) * 2];
                    mma16816(sacc[nt], Ah, bh);
                    mma16816(sacc[nt], Ah, bl);
                    mma16816(sacc[nt], Al, bh);
                }
            }
            // epilogue -> fp32 scores + bias
            const float* abr = s.ab + head * NTOK;
            int r0 = wm + (lane >> 2);
            #pragma unroll
            for (int nt = 0; nt < 4; ++nt) {
                int c0 = wn + nt * 8 + (lane & 3) * 2;
                #pragma unroll
                for (int h2 = 0; h2 < 2; ++h2) {
                    int r = r0 + h2 * 8;
                    if (r < NTOK) {
                        #pragma unroll
                        for (int q = 0; q < 2; ++q) {
                            int c = c0 + q;
                            if (c < NTOK)
                                s.u2.attn[r * ASF + c] =
                                    sacc[nt][h2 * 2 + q] * scale + abr[s.bidx[r * 49 + c]];
                        }
                    }
                }
            }
        }
        __syncthreads();

        // ================= softmax -> ath/atl (zero-padded K cols) =================
        for (int r = warp; r < NTOK; r += 8) {
            float a = s.u2.attn[r * ASF + lane];
            bool hasb = (lane + 32) < NTOK;
            float bv = hasb ? s.u2.attn[r * ASF + 32 + lane] : -1e30f;
            float mx = fmaxf(a, bv);
            #pragma unroll
            for (int off = 16; off > 0; off >>= 1)
                mx = fmaxf(mx, __shfl_xor_sync(0xffffffffu, mx, off));
            float ea = __expf(a - mx);
            float eb = hasb ? __expf(bv - mx) : 0.f;
            float sm = ea + eb;
            #pragma unroll
            for (int off = 16; off > 0; off >>= 1)
                sm += __shfl_xor_sync(0xffffffffu, sm, off);
            float inv = __frcp_rn(sm);
            float pa = ea * inv, pb = eb * inv;
            __nv_bfloat16 ph = __float2bfloat16(pa);
            s.u1.s2.ath[r * ATS + lane] = ph;
            s.u1.s2.atl[r * ATS + lane] = __float2bfloat16(pa - __bfloat162float(ph));
            if (hasb) {
                __nv_bfloat16 qh2 = __float2bfloat16(pb);
                s.u1.s2.ath[r * ATS + 32 + lane] = qh2;
                s.u1.s2.atl[r * ATS + 32 + lane] = __float2bfloat16(pb - __bfloat162float(qh2));
            }
            if (lane < 15) {
                __nv_bfloat16 z = __float2bfloat16(0.f);
                s.u1.s2.ath[r * ATS + 49 + lane] = z;
                s.u1.s2.atl[r * ATS + 49 + lane] = z;
            }
        }
        __syncthreads();

        // ================= attn @ v (mma, 3-term) =================
        {
            const int wm2 = (warp & 1) * 32, wn2 = (warp >> 1) * 32;
            float facc[2][4][4];
            #pragma unroll
            for (int mt = 0; mt < 2; ++mt)
                #pragma unroll
                for (int nt = 0; nt < 4; ++nt)
                    #pragma unroll
                    for (int q = 0; q < 4; ++q) facc[mt][nt][q] = 0.f;

            #pragma unroll
            for (int k16 = 0; k16 < 4; ++k16) {
                unsigned Ah[2][4], Al[2][4];
                #pragma unroll
                for (int mt = 0; mt < 2; ++mt) {
                    ldsm_x4(Ah[mt], s2u(&s.u1.s2.ath[(wm2 + mt * 16 + a_r) * ATS + k16 * 16 + a_c]));
                    ldsm_x4(Al[mt], s2u(&s.u1.s2.atl[(wm2 + mt * 16 + a_r) * ATS + k16 * 16 + a_c]));
                }
                unsigned Bh[2][4], Bl[2][4];
                #pragma unroll
                for (int g = 0; g < 2; ++g) {
                    unsigned addr_h = s2u(&s.vh[(k16 * 16 + (lane & 15)) * FST +
                                                wn2 + g * 16 + (lane >> 4) * 8]);
                    unsigned addr_l = s2u(&s.vl[(k16 * 16 + (lane & 15)) * FST +
                                                wn2 + g * 16 + (lane >> 4) * 8]);
                    ldsm_x4_t(Bh[g], addr_h);
                    ldsm_x4_t(Bl[g], addr_l);
                }
                #pragma unroll
                for (int mt = 0; mt < 2; ++mt)
                    #pragma unroll
                    for (int nt = 0; nt < 4; ++nt) {
                        const unsigned* bh = &Bh[nt >> 1][(nt & 1) * 2];
                        const unsigned* bl = &Bl[nt >> 1][(nt & 1) * 2];
                        mma16816(facc[mt][nt], Ah[mt], bh);
                        mma16816(facc[mt][nt], Ah[mt], bl);
                        mma16816(facc[mt][nt], Al[mt], bh);
                    }
            }
            // epilogue: new feat (ah/al) + relu to g_h
            #pragma unroll
            for (int mt = 0; mt < 2; ++mt)
                #pragma unroll
                for (int nt = 0; nt < 4; ++nt) {
                    int c0 = wn2 + nt * 8 + (lane & 3) * 2;
                    #pragma unroll
                    for (int h2 = 0; h2 < 2; ++h2) {
                        int r = wm2 + mt * 16 + (lane >> 2) + h2 * 8;
                        if (r < NTOK) {
                            float v0 = facc[mt][nt][h2 * 2 + 0];
                            float v1 = facc[mt][nt][h2 * 2 + 1];
                            unsigned hp, lp;
                            split2(v0, v1, hp, lp);
                            *reinterpret_cast<unsigned*>(&s.ah[r * FST + c0]) = hp;
                            *reinterpret_cast<unsigned*>(&s.al[r * FST + c0]) = lp;
                            float r0v = fmaxf(v0, 0.f), r1v = fmaxf(v1, 0.f);
                            unsigned ghp, glp;
                            split2(r0v, r1v, ghp, glp);
                            size_t off = ((size_t)b * NTOK + r) * CH + head * 128 + c0;
                            *reinterpret_cast<unsigned*>(&g_h_hi[off]) = ghp;
                            *reinterpret_cast<unsigned*>(&g_h_lo[off]) = glp;
                        }
                    }
                }
        }
        __syncthreads();
    }
}

// ==================== Phase B: projection (A via smem, B direct-global) ====================

#define PM 128
#define PN 64
#define PKC 32
#define AS 40

__global__ void __launch_bounds__(256, 2) proj_mma_kernel(
    const float* __restrict__ proj_g, const float* __restrict__ proj_b,
    const float* __restrict__ proj_m, const float* __restrict__ proj_v,
    float* __restrict__ out)
{
    __shared__ __align__(16) __nv_bfloat16 sAh[PM * AS];
    __shared__ __align__(16) __nv_bfloat16 sAl[PM * AS];
    __shared__ float sPs[PN], sPb[PN];

    const int t = threadIdx.x, lane = t & 31, warp = t >> 5;
    const int row0 = blockIdx.y * PM, col0 = blockIdx.x * PN;

    if (t < PN) {
        int o = col0 + t;
        float sc = proj_g[o] * rsqrtf(proj_v[o] + EPS);
        sPs[t] = sc;
        sPb[t] = proj_b[o] - proj_m[o] * sc;
    }

    const int ar0 = t >> 2;
    const int akk = (t & 3) * 8;

    float acc[2][4][4];
    #pragma unroll
    for (int mt = 0; mt < 2; ++mt)
        #pragma unroll
        for (int nt = 0; nt < 4; ++nt)
            #pragma unroll
            for (int q = 0; q < 4; ++q) acc[mt][nt][q] = 0.f;

    const int wm = (warp >> 1) * 32, wn = (warp & 1) * 32;
    const int a_r = lane & 15, a_c = (lane >> 4) * 8;
    const int nb = (col0 >> 3) + (wn >> 3);      // base n8 index for this warp

    uint4 rah0, rah1, ral0, ral1;
    {
        size_t base = (size_t)(row0 + ar0) * 512 + akk;
        rah0 = *reinterpret_cast<const uint4*>(&g_h_hi[base]);
        ral0 = *reinterpret_cast<const uint4*>(&g_h_lo[base]);
        rah1 = *reinterpret_cast<const uint4*>(&g_h_hi[base + (size_t)64 * 512]);
        ral1 = *reinterpret_cast<const uint4*>(&g_h_lo[base + (size_t)64 * 512]);
    }

    for (int kc = 0; kc < 16; ++kc) {
        __syncthreads();
        *reinterpret_cast<uint4*>(&sAh[ar0 * AS + akk]) = rah0;
        *reinterpret_cast<uint4*>(&sAl[ar0 * AS + akk]) = ral0;
        *reinterpret_cast<uint4*>(&sAh[(ar0 + 64) * AS + akk]) = rah1;
        *reinterpret_cast<uint4*>(&sAl[(ar0 + 64) * AS + akk]) = ral1;
        __syncthreads();
        if (kc < 15) {
            size_t base = (size_t)(row0 + ar0) * 512 + (kc + 1) * PKC + akk;
            rah0 = *reinterpret_cast<const uint4*>(&g_h_hi[base]);
            ral0 = *reinterpret_cast<const uint4*>(&g_h_lo[base]);
            rah1 = *reinterpret_cast<const uint4*>(&g_h_hi[base + (size_t)64 * 512]);
            ral1 = *reinterpret_cast<const uint4*>(&g_h_lo[base + (size_t)64 * 512]);
        }
        #pragma unroll
        for (int k16 = 0; k16 < 2; ++k16) {
            int ks = kc * 2 + k16;
            int kb = k16 * 16;
            unsigned Ah[2][4], Al[2][4];
            #pragma unroll
            for (int mt = 0; mt < 2; ++mt) {
                ldsm_x4(Ah[mt], s2u(&sAh[(wm + mt * 16 + a_r) * AS + kb + a_c]));
                ldsm_x4(Al[mt], s2u(&sAl[(wm + mt * 16 + a_r) * AS + kb + a_c]));
            }
            uint2 Bh[4], Bl[4];
            #pragma unroll
            for (int nt = 0; nt < 4; ++nt) {
                int bi = ((nb + nt) * 32 + ks) * 32 + lane;
                Bh[nt] = g_wB_hi[bi];
                Bl[nt] = g_wB_lo[bi];
            }
            #pragma unroll
            for (int mt = 0; mt < 2; ++mt)
                #pragma unroll
                for (int nt = 0; nt < 4; ++nt) {
                    const unsigned* bh = reinterpret_cast<const unsigned*>(&Bh[nt]);
                    const unsigned* bl = reinterpret_cast<const unsigned*>(&Bl[nt]);
                    mma16816(acc[mt][nt], Ah[mt], bh);
                    mma16816(acc[mt][nt], Ah[mt], bl);
                    mma16816(acc[mt][nt], Al[mt], bh);
                }
        }
    }

    const int er = lane >> 2, ec = (lane & 3) * 2;
    #pragma unroll
    for (int mt = 0; mt < 2; ++mt)
        #pragma unroll
        for (int nt = 0; nt < 4; ++nt) {
            int cl = wn + nt * 8 + ec;
            float s0 = sPs[cl], s1 = sPs[cl + 1];
            float b0 = sPb[cl], b1 = sPb[cl + 1];
            size_t gr = (size_t)(row0 + wm + mt * 16 + er) * 512 + col0 + cl;
            *reinterpret_cast<float2*>(&out[gr]) =
                make_float2(acc[mt][nt][0] * s0 + b0, acc[mt][nt][1] * s1 + b1);
            *reinterpret_cast<float2*>(&out[gr + (size_t)8 * 512]) =
                make_float2(acc[mt][nt][2] * s0 + b0, acc[mt][nt][3] * s1 + b1);
        }
}

// ==================== launch ====================

extern "C" void kernel_launch(void* const* d_in, const int* in_sizes, int n_in,
                              void* d_out, int out_size) {
    const float* x         = (const float*)d_in[0];
    const float* qkv_w     = (const float*)d_in[1];
    const float* qkv_g     = (const float*)d_in[2];
    const float* qkv_b     = (const float*)d_in[3];
    const float* qkv_m     = (const float*)d_in[4];
    const float* qkv_v     = (const float*)d_in[5];
    const float* dw_w      = (const float*)d_in[6];
    const float* dw_g      = (const float*)d_in[7];
    const float* dw_b      = (const float*)d_in[8];
    const float* dw_m      = (const float*)d_in[9];
    const float* dw_v      = (const float*)d_in[10];
    const float* proj_w    = (const float*)d_in[11];
    const float* proj_g    = (const float*)d_in[12];
    const float* proj_b    = (const float*)d_in[13];
    const float* proj_m    = (const float*)d_in[14];
    const float* proj_v    = (const float*)d_in[15];
    const float* attn_bias = (const float*)d_in[16];
    const int*   bias_idxs = (const int*)d_in[17];
    float* out = (float*)d_out;

    cudaFuncSetAttribute(cascade_kernel,
                         cudaFuncAttributeMaxDynamicSharedMemorySize,
                         (int)sizeof(SmemA));

    wsplit_kernel<<<256, 256>>>(proj_w);
    qkvsplit_kernel<<<192, 256>>>(qkv_w);

    cascade_kernel<<<BATCH, 256, sizeof(SmemA)>>>(
        x, qkv_g, qkv_b, qkv_m, qkv_v,
        dw_w, dw_g, dw_b, dw_m, dw_v, attn_bias, bias_idxs);

    proj_mma_kernel<<<dim3(8, 784), 256>>>(proj_g, proj_b, proj_m, proj_v, out);
}

// round 5
// speedup vs baseline: 4.2171x; 1.0674x over previous
#include <cuda_runtime.h>
#include <cuda_bf16.h>

#define BATCH   2048
#define NTOK    49
#define CH      512
#define NHEADS  4
#define KDIM    32
#define DV      128
#define QO      192
#define EPS     1e-5f
#define FST     136      // feat / v row stride (bf16)
#define KQS     40       // k / q row stride (bf16)
#define ATS     72       // attn-prob row stride (bf16)
#define ASF     52       // attn fp32 score row stride
#define YQS     36       // conv-input fp32 stride
#define NROWS   ((size_t)BATCH * NTOK)   // 100352

// -------- global scratch --------
// h in A-fragment-native layout: [row][kstep(32)][quad(4)] uint4
//   uint4 = {hi(c,c+1), hi(c+8,c+9), lo(c,c+1), lo(c+8,c+9)}, c = quad*2, col = kstep*16 + ...
__device__ __align__(16) uint4 g_hA[NROWS * 128];
// proj weights, B-fragment permuted: [n8(64)][k16(32)][lane(32)] uint4 {bh.x,bh.y,bl.x,bl.y}
__device__ __align__(16) uint4 g_wB[64 * 32 * 32];
// qkv weights, B-fragment permuted: [head][j(24)][kstep(8)][lane(32)] uint2
__device__ __align__(16) uint2 g_qwB_hi[NHEADS * 24 * 8 * 32];
__device__ __align__(16) uint2 g_qwB_lo[NHEADS * 24 * 8 * 32];

// ==================== mma helpers ====================
__device__ __forceinline__ unsigned s2u(const void* p) {
    return (unsigned)__cvta_generic_to_shared(p);
}
__device__ __forceinline__ void ldsm_x4(unsigned* r, unsigned addr) {
    asm volatile("ldmatrix.sync.aligned.m8n8.x4.shared.b16 {%0,%1,%2,%3}, [%4];"
        : "=r"(r[0]), "=r"(r[1]), "=r"(r[2]), "=r"(r[3]) : "r"(addr));
}
__device__ __forceinline__ void ldsm_x4_t(unsigned* r, unsigned addr) {
    asm volatile("ldmatrix.sync.aligned.m8n8.x4.trans.shared.b16 {%0,%1,%2,%3}, [%4];"
        : "=r"(r[0]), "=r"(r[1]), "=r"(r[2]), "=r"(r[3]) : "r"(addr));
}
__device__ __forceinline__ void mma16816(float* c, const unsigned* a, const unsigned* b) {
    asm volatile("mma.sync.aligned.m16n8k16.row.col.f32.bf16.bf16.f32 "
        "{%0,%1,%2,%3}, {%4,%5,%6,%7}, {%8,%9}, {%0,%1,%2,%3};"
        : "+f"(c[0]), "+f"(c[1]), "+f"(c[2]), "+f"(c[3])
        : "r"(a[0]), "r"(a[1]), "r"(a[2]), "r"(a[3]), "r"(b[0]), "r"(b[1]));
}
__device__ __forceinline__ unsigned packbf2(float a, float b) {
    __nv_bfloat162 p = __halves2bfloat162(__float2bfloat16(a), __float2bfloat16(b));
    return *reinterpret_cast<unsigned*>(&p);
}
__device__ __forceinline__ void split2(float v0, float v1, unsigned& hp, unsigned& lp) {
    __nv_bfloat16 h0 = __float2bfloat16(v0), h1 = __float2bfloat16(v1);
    hp = (unsigned)__bfloat16_as_ushort(h0) | ((unsigned)__bfloat16_as_ushort(h1) << 16);
    lp = packbf2(v0 - __bfloat162float(h0), v1 - __bfloat162float(h1));
}

// ==================== prep kernels ====================
__global__ void wsplit_kernel(const float* __restrict__ w) {
    int i = blockIdx.x * 256 + threadIdx.x;       // 65536
    int j0 = i >> 10;          // n8 tile
    int s_ = (i >> 5) & 31;    // k16 step
    int l  = i & 31;
    int n  = j0 * 8 + (l >> 2);
    int k0 = s_ * 16 + (l & 3) * 2;
    float a0 = w[n * 512 + k0],     a1 = w[n * 512 + k0 + 1];
    float a2 = w[n * 512 + k0 + 8], a3 = w[n * 512 + k0 + 9];
    uint4 p;
    split2(a0, a1, p.x, p.z);
    split2(a2, a3, p.y, p.w);
    g_wB[i] = p;
}

__global__ void qkvsplit_kernel(const float* __restrict__ w) {
    int i = blockIdx.x * 256 + threadIdx.x;       // 4*192*64 = 49152
    int h = i / (192 * 64);
    int rem = i % (192 * 64);
    int n = rem / 64;
    int p = rem % 64;
    float v0 = w[((size_t)h * 192 + n) * 128 + p * 2];
    float v1 = w[((size_t)h * 192 + n) * 128 + p * 2 + 1];
    unsigned hi, lo;
    split2(v0, v1, hi, lo);
    int j = n >> 3, kstep = p >> 3, q = p & 7;
    int r = q >> 2, lm4 = q & 3;
    int lane = (n & 7) * 4 + lm4;
    int base = ((h * 24 + j) * 8 + kstep) * 32 + lane;
    reinterpret_cast<unsigned*>(g_qwB_hi)[base * 2 + r] = hi;
    reinterpret_cast<unsigned*>(g_qwB_lo)[base * 2 + r] = lo;
}

// ==================== Phase A: cascaded heads (all-mma) ====================

struct __align__(16) SmemA {
    __nv_bfloat16 ah[64 * FST], al[64 * FST];   // feat hi/lo
    __nv_bfloat16 vh[64 * FST], vl[64 * FST];   // v hi/lo [m][d]
    union U1 {
        struct { __nv_bfloat16 kh[64 * KQS], kl[64 * KQS],
                               qh[64 * KQS], ql[64 * KQS]; } s1;
        struct { __nv_bfloat16 ath[64 * ATS], atl[64 * ATS]; } s2;
    } u1;
    union U2 { float attn[49 * ASF]; float yq[49 * YQS]; } u2;
    float dww[25 * 32];
    float qscale[QO], qbias[QO];
    float dws[KDIM], dwb[KDIM];
    float ab[NHEADS * NTOK];
    unsigned char bidx[NTOK * NTOK];
};

__global__ void __launch_bounds__(256, 2) cascade_kernel(
    const float* __restrict__ x,
    const float* __restrict__ qkv_g,  const float* __restrict__ qkv_b,
    const float* __restrict__ qkv_m,  const float* __restrict__ qkv_v,
    const float* __restrict__ dw_w,   const float* __restrict__ dw_g,
    const float* __restrict__ dw_b,   const float* __restrict__ dw_m,
    const float* __restrict__ dw_v,   const float* __restrict__ attn_bias,
    const int* __restrict__ bias_idxs)
{
    extern __shared__ unsigned char smem_raw[];
    SmemA& s = *reinterpret_cast<SmemA*>(smem_raw);
    const int t    = threadIdx.x;
    const int b    = blockIdx.x;
    const int lane = t & 31;
    const int warp = t >> 5;
    const float scale = rsqrtf((float)KDIM);
    const size_t xoff = (size_t)b * NTOK * CH;

    for (int j = t; j < NTOK * NTOK; j += 256) s.bidx[j] = (unsigned char)bias_idxs[j];
    for (int j = t; j < NHEADS * NTOK; j += 256) s.ab[j] = attn_bias[j];
    for (int j = t; j < 15 * FST; j += 256) {
        __nv_bfloat16 z = __float2bfloat16(0.f);
        s.ah[49 * FST + j] = z; s.al[49 * FST + j] = z;
        s.vh[49 * FST + j] = z; s.vl[49 * FST + j] = z;
    }

    const int a_r = lane & 15, a_c = (lane >> 4) * 8;
    const int b_r = (lane & 7) + ((lane & 16) ? 8 : 0);
    const int b_c = (lane & 8) ? 8 : 0;

    for (int head = 0; head < NHEADS; ++head) {
        // ---- feat update + hi/lo split ----
        for (int jdx = t; jdx < NTOK * 128; jdx += 256) {
            int n = jdx >> 7, d = jdx & 127;
            float v;
            if (head == 0) {
                v = x[xoff + n * CH + d];
            } else {
                v = __bfloat162float(s.ah[n * FST + d]) +
                    __bfloat162float(s.al[n * FST + d]) +
                    x[xoff + n * CH + head * 128 + d];
            }
            __nv_bfloat16 hv = __float2bfloat16(v);
            s.ah[n * FST + d] = hv;
            s.al[n * FST + d] = __float2bfloat16(v - __bfloat162float(hv));
        }
        // ---- BN folds ----
        if (t < QO) {
            float sc = qkv_g[head * QO + t] * rsqrtf(qkv_v[head * QO + t] + EPS);
            s.qscale[t] = sc;
            s.qbias[t]  = qkv_b[head * QO + t] - qkv_m[head * QO + t] * sc;
        } else if (t < QO + KDIM) {
            int c = t - QO;
            float sc = dw_g[head * KDIM + c] * rsqrtf(dw_v[head * KDIM + c] + EPS);
            s.dws[c] = sc;
            s.dwb[c] = dw_b[head * KDIM + c] - dw_m[head * KDIM + c] * sc;
        }
        for (int j = t; j < KDIM * 25; j += 256) {
            int c = j / 25, tap = j % 25;
            s.dww[tap * 32 + c] = dw_w[(head * KDIM + c) * 25 + tap];
        }
        __syncthreads();

        // ================= qkv GEMM (mma, 3-term) =================
        {
            float qacc[4][3][4];
            #pragma unroll
            for (int m = 0; m < 4; ++m)
                #pragma unroll
                for (int j = 0; j < 3; ++j)
                    #pragma unroll
                    for (int q = 0; q < 4; ++q) qacc[m][j][q] = 0.f;

            for (int k = 0; k < 8; ++k) {
                uint2 bh[3], bl[3];
                #pragma unroll
                for (int j = 0; j < 3; ++j) {
                    int bi = ((head * 24 + warp * 3 + j) * 8 + k) * 32 + lane;
                    bh[j] = g_qwB_hi[bi];
                    bl[j] = g_qwB_lo[bi];
                }
                #pragma unroll
                for (int m = 0; m < 4; ++m) {
                    unsigned Ah[4], Al[4];
                    ldsm_x4(Ah, s2u(&s.ah[(m * 16 + a_r) * FST + k * 16 + a_c]));
                    ldsm_x4(Al, s2u(&s.al[(m * 16 + a_r) * FST + k * 16 + a_c]));
                    #pragma unroll
                    for (int j = 0; j < 3; ++j) {
                        mma16816(qacc[m][j], Ah, reinterpret_cast<const unsigned*>(&bh[j]));
                        mma16816(qacc[m][j], Ah, reinterpret_cast<const unsigned*>(&bl[j]));
                        mma16816(qacc[m][j], Al, reinterpret_cast<const unsigned*>(&bh[j]));
                    }
                }
            }
            // epilogue: BN fold -> yq (q fp32) | kh/kl | vh/vl
            #pragma unroll
            for (int m = 0; m < 4; ++m) {
                int rb = m * 16 + (lane >> 2);
                #pragma unroll
                for (int j = 0; j < 3; ++j) {
                    int c0 = warp * 24 + j * 8 + (lane & 3) * 2;
                    float sc0 = s.qscale[c0], sc1 = s.qscale[c0 + 1];
                    float bb0 = s.qbias[c0],  bb1 = s.qbias[c0 + 1];
                    #pragma unroll
                    for (int h2 = 0; h2 < 2; ++h2) {
                        int r = rb + h2 * 8;
                        if (r < NTOK) {
                            float y0 = qacc[m][j][h2 * 2 + 0] * sc0 + bb0;
                            float y1 = qacc[m][j][h2 * 2 + 1] * sc1 + bb1;
                            if (c0 < 32) {
                                s.u2.yq[r * YQS + c0]     = y0;
                                s.u2.yq[r * YQS + c0 + 1] = y1;
                            } else if (c0 < 64) {
                                unsigned hp, lp;
                                split2(y0, y1, hp, lp);
                                *reinterpret_cast<unsigned*>(&s.u1.s1.kh[r * KQS + c0 - 32]) = hp;
                                *reinterpret_cast<unsigned*>(&s.u1.s1.kl[r * KQS + c0 - 32]) = lp;
                            } else {
                                unsigned hp, lp;
                                split2(y0, y1, hp, lp);
                                *reinterpret_cast<unsigned*>(&s.vh[r * FST + c0 - 64]) = hp;
                                *reinterpret_cast<unsigned*>(&s.vl[r * FST + c0 - 64]) = lp;
                            }
                        }
                    }
                }
            }
        }
        __syncthreads();

        // ================= depthwise 5x5 conv (+BN) -> qh/ql =================
        for (int idx = t; idx < NTOK * KDIM; idx += 256) {
            int n = idx >> 5, c = idx & 31;
            int r = n / 7, sc_ = n % 7;
            float sum = 0.f;
            #pragma unroll
            for (int a = 0; a < 5; ++a) {
                int rr = r + a - 2;
                if ((unsigned)rr < 7u) {
                    #pragma unroll
                    for (int bb = 0; bb < 5; ++bb) {
                        int ss = sc_ + bb - 2;
                        if ((unsigned)ss < 7u)
                            sum += s.u2.yq[(rr * 7 + ss) * YQS + c] * s.dww[(a * 5 + bb) * 32 + c];
                    }
                }
            }
            float qv = sum * s.dws[c] + s.dwb[c];
            __nv_bfloat16 hv = __float2bfloat16(qv);
            s.u1.s1.qh[n * KQS + c] = hv;
            s.u1.s1.ql[n * KQS + c] = __float2bfloat16(qv - __bfloat162float(hv));
        }
        __syncthreads();

        // ================= qk scores (mma, 3-term) =================
        {
            const int wm = (warp & 3) * 16, wn = (warp >> 2) * 32;
            float sacc[4][4];
            #pragma unroll
            for (int nt = 0; nt < 4; ++nt)
                #pragma unroll
                for (int q = 0; q < 4; ++q) sacc[nt][q] = 0.f;

            #pragma unroll
            for (int k16 = 0; k16 < 2; ++k16) {
                unsigned Ah[4], Al[4];
                ldsm_x4(Ah, s2u(&s.u1.s1.qh[(wm + a_r) * KQS + k16 * 16 + a_c]));
                ldsm_x4(Al, s2u(&s.u1.s1.ql[(wm + a_r) * KQS + k16 * 16 + a_c]));
                unsigned Bh[2][4], Bl[2][4];
                #pragma unroll
                for (int g = 0; g < 2; ++g) {
                    ldsm_x4(Bh[g], s2u(&s.u1.s1.kh[(wn + g * 16 + b_r) * KQS + k16 * 16 + b_c]));
                    ldsm_x4(Bl[g], s2u(&s.u1.s1.kl[(wn + g * 16 + b_r) * KQS + k16 * 16 + b_c]));
                }
                #pragma unroll
                for (int nt = 0; nt < 4; ++nt) {
                    const unsigned* bh = &Bh[nt >> 1][(nt & 1) * 2];
                    const unsigned* bl = &Bl[nt >> 1][(nt & 1) * 2];
                    mma16816(sacc[nt], Ah, bh);
                    mma16816(sacc[nt], Ah, bl);
                    mma16816(sacc[nt], Al, bh);
                }
            }
            const float* abr = s.ab + head * NTOK;
            int r0 = wm + (lane >> 2);
            #pragma unroll
            for (int nt = 0; nt < 4; ++nt) {
                int c0 = wn + nt * 8 + (lane & 3) * 2;
                #pragma unroll
                for (int h2 = 0; h2 < 2; ++h2) {
                    int r = r0 + h2 * 8;
                    if (r < NTOK) {
                        #pragma unroll
                        for (int q = 0; q < 2; ++q) {
                            int c = c0 + q;
                            if (c < NTOK)
                                s.u2.attn[r * ASF + c] =
                                    sacc[nt][h2 * 2 + q] * scale + abr[s.bidx[r * 49 + c]];
                        }
                    }
                }
            }
        }
        __syncthreads();

        // ================= softmax -> ath/atl =================
        for (int r = warp; r < NTOK; r += 8) {
            float a = s.u2.attn[r * ASF + lane];
            bool hasb = (lane + 32) < NTOK;
            float bv = hasb ? s.u2.attn[r * ASF + 32 + lane] : -1e30f;
            float mx = fmaxf(a, bv);
            #pragma unroll
            for (int off = 16; off > 0; off >>= 1)
                mx = fmaxf(mx, __shfl_xor_sync(0xffffffffu, mx, off));
            float ea = __expf(a - mx);
            float eb = hasb ? __expf(bv - mx) : 0.f;
            float sm = ea + eb;
            #pragma unroll
            for (int off = 16; off > 0; off >>= 1)
                sm += __shfl_xor_sync(0xffffffffu, sm, off);
            float inv = __frcp_rn(sm);
            float pa = ea * inv, pb = eb * inv;
            __nv_bfloat16 ph = __float2bfloat16(pa);
            s.u1.s2.ath[r * ATS + lane] = ph;
            s.u1.s2.atl[r * ATS + lane] = __float2bfloat16(pa - __bfloat162float(ph));
            if (hasb) {
                __nv_bfloat16 qh2 = __float2bfloat16(pb);
                s.u1.s2.ath[r * ATS + 32 + lane] = qh2;
                s.u1.s2.atl[r * ATS + 32 + lane] = __float2bfloat16(pb - __bfloat162float(qh2));
            }
            if (lane < 15) {
                __nv_bfloat16 z = __float2bfloat16(0.f);
                s.u1.s2.ath[r * ATS + 49 + lane] = z;
                s.u1.s2.atl[r * ATS + 49 + lane] = z;
            }
        }
        __syncthreads();

        // ================= attn @ v (mma, 3-term) =================
        {
            const int wm2 = (warp & 1) * 32, wn2 = (warp >> 1) * 32;
            float facc[2][4][4];
            #pragma unroll
            for (int mt = 0; mt < 2; ++mt)
                #pragma unroll
                for (int nt = 0; nt < 4; ++nt)
                    #pragma unroll
                    for (int q = 0; q < 4; ++q) facc[mt][nt][q] = 0.f;

            #pragma unroll
            for (int k16 = 0; k16 < 4; ++k16) {
                unsigned Ah[2][4], Al[2][4];
                #pragma unroll
                for (int mt = 0; mt < 2; ++mt) {
                    ldsm_x4(Ah[mt], s2u(&s.u1.s2.ath[(wm2 + mt * 16 + a_r) * ATS + k16 * 16 + a_c]));
                    ldsm_x4(Al[mt], s2u(&s.u1.s2.atl[(wm2 + mt * 16 + a_r) * ATS + k16 * 16 + a_c]));
                }
                unsigned Bh[2][4], Bl[2][4];
                #pragma unroll
                for (int g = 0; g < 2; ++g) {
                    unsigned addr_h = s2u(&s.vh[(k16 * 16 + (lane & 15)) * FST +
                                                wn2 + g * 16 + (lane >> 4) * 8]);
                    unsigned addr_l = s2u(&s.vl[(k16 * 16 + (lane & 15)) * FST +
                                                wn2 + g * 16 + (lane >> 4) * 8]);
                    ldsm_x4_t(Bh[g], addr_h);
                    ldsm_x4_t(Bl[g], addr_l);
                }
                #pragma unroll
                for (int mt = 0; mt < 2; ++mt)
                    #pragma unroll
                    for (int nt = 0; nt < 4; ++nt) {
                        const unsigned* bh = &Bh[nt >> 1][(nt & 1) * 2];
                        const unsigned* bl = &Bl[nt >> 1][(nt & 1) * 2];
                        mma16816(facc[mt][nt], Ah[mt], bh);
                        mma16816(facc[mt][nt], Ah[mt], bl);
                        mma16816(facc[mt][nt], Al[mt], bh);
                    }
            }
            // epilogue: new feat (ah/al) + relu to g_hA (fragment-native layout)
            #pragma unroll
            for (int mt = 0; mt < 2; ++mt)
                #pragma unroll
                for (int nt = 0; nt < 4; ++nt) {
                    int c0 = wn2 + nt * 8 + (lane & 3) * 2;
                    int C  = head * 128 + c0;
                    int kstep = C >> 4, jj = C & 15;
                    int quad = (jj < 8) ? (jj >> 1) : ((jj - 8) >> 1);
                    int word = (jj < 8) ? 0 : 1;
                    #pragma unroll
                    for (int h2 = 0; h2 < 2; ++h2) {
                        int r = wm2 + mt * 16 + (lane >> 2) + h2 * 8;
                        if (r < NTOK) {
                            float v0 = facc[mt][nt][h2 * 2 + 0];
                            float v1 = facc[mt][nt][h2 * 2 + 1];
                            unsigned hp, lp;
                            split2(v0, v1, hp, lp);
                            *reinterpret_cast<unsigned*>(&s.ah[r * FST + c0]) = hp;
                            *reinterpret_cast<unsigned*>(&s.al[r * FST + c0]) = lp;
                            float r0v = fmaxf(v0, 0.f), r1v = fmaxf(v1, 0.f);
                            unsigned ghp, glp;
                            split2(r0v, r1v, ghp, glp);
                            size_t row = (size_t)b * NTOK + r;
                            unsigned* up = reinterpret_cast<unsigned*>(
                                &g_hA[row * 128 + kstep * 4 + quad]);
                            up[word]     = ghp;
                            up[word + 2] = glp;
                        }
                    }
                }
        }
        __syncthreads();
    }
}

// ==================== Phase B: projection — pure LDG + mma, no smem mainloop ====================

__global__ void __launch_bounds__(256, 2) proj_mma_kernel(
    const float* __restrict__ proj_g, const float* __restrict__ proj_b,
    const float* __restrict__ proj_m, const float* __restrict__ proj_v,
    float* __restrict__ out)
{
    __shared__ float sPs[64], sPb[64];

    const int t = threadIdx.x, lane = t & 31, warp = t >> 5;
    const int row0 = blockIdx.y * 128, col0 = blockIdx.x * 64;

    if (t < 64) {
        int o = col0 + t;
        float sc = proj_g[o] * rsqrtf(proj_v[o] + EPS);
        sPs[t] = sc;
        sPb[t] = proj_b[o] - proj_m[o] * sc;
    }
    __syncthreads();

    const int wm = (warp >> 1) * 32, wn = (warp & 1) * 32;
    const int nb = (col0 >> 3) + (wn >> 3);

    float acc[2][4][4];
    #pragma unroll
    for (int mt = 0; mt < 2; ++mt)
        #pragma unroll
        for (int nt = 0; nt < 4; ++nt)
            #pragma unroll
            for (int q = 0; q < 4; ++q) acc[mt][nt][q] = 0.f;

    const int ar = lane >> 2;     // 0..7
    const int aq = lane & 3;      // quad

    for (int ks = 0; ks < 32; ++ks) {
        // A fragments direct from global (hi+lo fused in uint4)
        unsigned Ah[2][4], Al[2][4];
        #pragma unroll
        for (int mt = 0; mt < 2; ++mt) {
            size_t r0 = (size_t)(row0 + wm + mt * 16 + ar);
            uint4 U0 = g_hA[r0 * 128 + ks * 4 + aq];
            uint4 U1 = g_hA[(r0 + 8) * 128 + ks * 4 + aq];
            Ah[mt][0] = U0.x; Ah[mt][1] = U1.x; Ah[mt][2] = U0.y; Ah[mt][3] = U1.y;
            Al[mt][0] = U0.z; Al[mt][1] = U1.z; Al[mt][2] = U0.w; Al[mt][3] = U1.w;
        }
        // B fragments direct from global
        uint4 W[4];
        #pragma unroll
        for (int nt = 0; nt < 4; ++nt)
            W[nt] = g_wB[((nb + nt) * 32 + ks) * 32 + lane];

        #pragma unroll
        for (int mt = 0; mt < 2; ++mt)
            #pragma unroll
            for (int nt = 0; nt < 4; ++nt) {
                unsigned bh[2] = {W[nt].x, W[nt].y};
                unsigned bl[2] = {W[nt].z, W[nt].w};
                mma16816(acc[mt][nt], Ah[mt], bh);
                mma16816(acc[mt][nt], Ah[mt], bl);
                mma16816(acc[mt][nt], Al[mt], bh);
            }
    }

    const int er = lane >> 2, ec = (lane & 3) * 2;
    #pragma unroll
    for (int mt = 0; mt < 2; ++mt)
        #pragma unroll
        for (int nt = 0; nt < 4; ++nt) {
            int cl = wn + nt * 8 + ec;
            float s0 = sPs[cl], s1 = sPs[cl + 1];
            float b0 = sPb[cl], b1 = sPb[cl + 1];
            size_t gr = (size_t)(row0 + wm + mt * 16 + er) * 512 + col0 + cl;
            *reinterpret_cast<float2*>(&out[gr]) =
                make_float2(acc[mt][nt][0] * s0 + b0, acc[mt][nt][1] * s1 + b1);
            *reinterpret_cast<float2*>(&out[gr + (size_t)8 * 512]) =
                make_float2(acc[mt][nt][2] * s0 + b0, acc[mt][nt][3] * s1 + b1);
        }
}

// ==================== launch ====================

extern "C" void kernel_launch(void* const* d_in, const int* in_sizes, int n_in,
                              void* d_out, int out_size) {
    const float* x         = (const float*)d_in[0];
    const float* qkv_w     = (const float*)d_in[1];
    const float* qkv_g     = (const float*)d_in[2];
    const float* qkv_b     = (const float*)d_in[3];
    const float* qkv_m     = (const float*)d_in[4];
    const float* qkv_v     = (const float*)d_in[5];
    const float* dw_w      = (const float*)d_in[6];
    const float* dw_g      = (const float*)d_in[7];
    const float* dw_b      = (const float*)d_in[8];
    const float* dw_m      = (const float*)d_in[9];
    const float* dw_v      = (const float*)d_in[10];
    const float* proj_w    = (const float*)d_in[11];
    const float* proj_g    = (const float*)d_in[12];
    const float* proj_b    = (const float*)d_in[13];
    const float* proj_m    = (const float*)d_in[14];
    const float* proj_v    = (const float*)d_in[15];
    const float* attn_bias = (const float*)d_in[16];
    const int*   bias_idxs = (const int*)d_in[17];
    float* out = (float*)d_out;

    cudaFuncSetAttribute(cascade_kernel,
                         cudaFuncAttributeMaxDynamicSharedMemorySize,
                         (int)sizeof(SmemA));

    wsplit_kernel<<<256, 256>>>(proj_w);
    qkvsplit_kernel<<<192, 256>>>(qkv_w);

    cascade_kernel<<<BATCH, 256, sizeof(SmemA)>>>(
        x, qkv_g, qkv_b, qkv_m, qkv_v,
        dw_w, dw_g, dw_b, dw_m, dw_v, attn_bias, bias_idxs);

    proj_mma_kernel<<<dim3(8, 784), 256>>>(proj_g, proj_b, proj_m, proj_v, out);
}

// round 6
// speedup vs baseline: 4.2423x; 1.0060x over previous
#include <cuda_runtime.h>
#include <cuda_bf16.h>

#define BATCH   2048
#define NTOK    49
#define CH      512
#define NHEADS  4
#define KDIM    32
#define DV      128
#define QO      192
#define EPS     1e-5f
#define FST     136      // feat / v row stride (bf16)
#define KQS     40       // k / q row stride (bf16)
#define ATS     72       // attn-prob row stride (bf16)
#define ASF     52       // attn fp32 score row stride
#define YQS     36       // conv-input fp32 stride
#define NROWS   ((size_t)BATCH * NTOK)   // 100352

// -------- global scratch --------
// h in proj-A-fragment tiled layout: [m16tile(6272)][kstep(32)][r16(16)][quad(4)] uint4
//   uint4 = {hi(c,c+1), hi(c+8,c+9), lo(c,c+1), lo(c+8,c+9)}
__device__ __align__(16) uint4 g_hA[NROWS * 128];
// proj weights, B-fragment permuted: [n8(64)][k16(32)][lane(32)] uint4 {bh.x,bh.y,bl.x,bl.y}
__device__ __align__(16) uint4 g_wB[64 * 32 * 32];
// qkv weights, B-fragment permuted: [head][j(24)][kstep(8)][lane(32)] uint2
__device__ __align__(16) uint2 g_qwB_hi[NHEADS * 24 * 8 * 32];
__device__ __align__(16) uint2 g_qwB_lo[NHEADS * 24 * 8 * 32];

// ==================== helpers ====================
__device__ __forceinline__ unsigned s2u(const void* p) {
    return (unsigned)__cvta_generic_to_shared(p);
}
__device__ __forceinline__ void ldsm_x4(unsigned* r, unsigned addr) {
    asm volatile("ldmatrix.sync.aligned.m8n8.x4.shared.b16 {%0,%1,%2,%3}, [%4];"
        : "=r"(r[0]), "=r"(r[1]), "=r"(r[2]), "=r"(r[3]) : "r"(addr));
}
__device__ __forceinline__ void ldsm_x4_t(unsigned* r, unsigned addr) {
    asm volatile("ldmatrix.sync.aligned.m8n8.x4.trans.shared.b16 {%0,%1,%2,%3}, [%4];"
        : "=r"(r[0]), "=r"(r[1]), "=r"(r[2]), "=r"(r[3]) : "r"(addr));
}
__device__ __forceinline__ void mma16816(float* c, const unsigned* a, const unsigned* b) {
    asm volatile("mma.sync.aligned.m16n8k16.row.col.f32.bf16.bf16.f32 "
        "{%0,%1,%2,%3}, {%4,%5,%6,%7}, {%8,%9}, {%0,%1,%2,%3};"
        : "+f"(c[0]), "+f"(c[1]), "+f"(c[2]), "+f"(c[3])
        : "r"(a[0]), "r"(a[1]), "r"(a[2]), "r"(a[3]), "r"(b[0]), "r"(b[1]));
}
__device__ __forceinline__ unsigned packbf2(float a, float b) {
    __nv_bfloat162 p = __halves2bfloat162(__float2bfloat16(a), __float2bfloat16(b));
    return *reinterpret_cast<unsigned*>(&p);
}
__device__ __forceinline__ void split2(float v0, float v1, unsigned& hp, unsigned& lp) {
    __nv_bfloat16 h0 = __float2bfloat16(v0), h1 = __float2bfloat16(v1);
    hp = (unsigned)__bfloat16_as_ushort(h0) | ((unsigned)__bfloat16_as_ushort(h1) << 16);
    lp = packbf2(v0 - __bfloat162float(h0), v1 - __bfloat162float(h1));
}
__device__ __forceinline__ void pref_l1(const void* p) {
    asm volatile("prefetch.global.L1 [%0];" :: "l"(p));
}

// ==================== prep kernels ====================
__global__ void wsplit_kernel(const float* __restrict__ w) {
    int i = blockIdx.x * 256 + threadIdx.x;       // 65536
    int j0 = i >> 10;
    int s_ = (i >> 5) & 31;
    int l  = i & 31;
    int n  = j0 * 8 + (l >> 2);
    int k0 = s_ * 16 + (l & 3) * 2;
    float a0 = w[n * 512 + k0],     a1 = w[n * 512 + k0 + 1];
    float a2 = w[n * 512 + k0 + 8], a3 = w[n * 512 + k0 + 9];
    uint4 p;
    split2(a0, a1, p.x, p.z);
    split2(a2, a3, p.y, p.w);
    g_wB[i] = p;
}

__global__ void qkvsplit_kernel(const float* __restrict__ w) {
    int i = blockIdx.x * 256 + threadIdx.x;       // 49152
    int h = i / (192 * 64);
    int rem = i % (192 * 64);
    int n = rem / 64;
    int p = rem % 64;
    float v0 = w[((size_t)h * 192 + n) * 128 + p * 2];
    float v1 = w[((size_t)h * 192 + n) * 128 + p * 2 + 1];
    unsigned hi, lo;
    split2(v0, v1, hi, lo);
    int j = n >> 3, kstep = p >> 3, q = p & 7;
    int r = q >> 2, lm4 = q & 3;
    int lane = (n & 7) * 4 + lm4;
    int base = ((h * 24 + j) * 8 + kstep) * 32 + lane;
    reinterpret_cast<unsigned*>(g_qwB_hi)[base * 2 + r] = hi;
    reinterpret_cast<unsigned*>(g_qwB_lo)[base * 2 + r] = lo;
}

// ==================== Phase A: cascaded heads (all-mma) ====================

struct __align__(16) SmemA {
    __nv_bfloat16 ah[64 * FST], al[64 * FST];
    __nv_bfloat16 vh[64 * FST], vl[64 * FST];
    union U1 {
        struct { __nv_bfloat16 kh[64 * KQS], kl[64 * KQS],
                               qh[64 * KQS], ql[64 * KQS]; } s1;
        struct { __nv_bfloat16 ath[64 * ATS], atl[64 * ATS]; } s2;
    } u1;
    union U2 { float attn[49 * ASF]; float yq[49 * YQS]; } u2;
    float dww[25 * 32];
    float qscale[QO], qbias[QO];
    float dws[KDIM], dwb[KDIM];
    float ab[NHEADS * NTOK];
};

__global__ void __launch_bounds__(256, 2) cascade_kernel(
    const float* __restrict__ x,
    const float* __restrict__ qkv_g,  const float* __restrict__ qkv_b,
    const float* __restrict__ qkv_m,  const float* __restrict__ qkv_v,
    const float* __restrict__ dw_w,   const float* __restrict__ dw_g,
    const float* __restrict__ dw_b,   const float* __restrict__ dw_m,
    const float* __restrict__ dw_v,   const float* __restrict__ attn_bias)
{
    extern __shared__ unsigned char smem_raw[];
    SmemA& s = *reinterpret_cast<SmemA*>(smem_raw);
    const int t    = threadIdx.x;
    const int b    = blockIdx.x;
    const int lane = t & 31;
    const int warp = t >> 5;
    const float scale = rsqrtf((float)KDIM);
    const size_t xoff = (size_t)b * NTOK * CH;

    for (int j = t; j < NHEADS * NTOK; j += 256) s.ab[j] = attn_bias[j];
    for (int j = t; j < 15 * FST; j += 256) {
        __nv_bfloat16 z = __float2bfloat16(0.f);
        s.ah[49 * FST + j] = z; s.al[49 * FST + j] = z;
        s.vh[49 * FST + j] = z; s.vl[49 * FST + j] = z;
    }
    // prefetch head-0 x chunk (196 lines of 128B)
    if (t < 196) pref_l1(&x[xoff + (t >> 2) * CH + (t & 3) * 32]);

    const int a_r = lane & 15, a_c = (lane >> 4) * 8;
    const int b_r = (lane & 7) + ((lane & 16) ? 8 : 0);
    const int b_c = (lane & 8) ? 8 : 0;

    for (int head = 0; head < NHEADS; ++head) {
        // ---- feat update + hi/lo split ----
        for (int jdx = t; jdx < NTOK * 128; jdx += 256) {
            int n = jdx >> 7, d = jdx & 127;
            float v;
            if (head == 0) {
                v = x[xoff + n * CH + d];
            } else {
                v = __bfloat162float(s.ah[n * FST + d]) +
                    __bfloat162float(s.al[n * FST + d]) +
                    x[xoff + n * CH + head * 128 + d];
            }
            __nv_bfloat16 hv = __float2bfloat16(v);
            s.ah[n * FST + d] = hv;
            s.al[n * FST + d] = __float2bfloat16(v - __bfloat162float(hv));
        }
        // ---- BN folds ----
        if (t < QO) {
            float sc = qkv_g[head * QO + t] * rsqrtf(qkv_v[head * QO + t] + EPS);
            s.qscale[t] = sc;
            s.qbias[t]  = qkv_b[head * QO + t] - qkv_m[head * QO + t] * sc;
        } else if (t < QO + KDIM) {
            int c = t - QO;
            float sc = dw_g[head * KDIM + c] * rsqrtf(dw_v[head * KDIM + c] + EPS);
            s.dws[c] = sc;
            s.dwb[c] = dw_b[head * KDIM + c] - dw_m[head * KDIM + c] * sc;
        }
        for (int j = t; j < KDIM * 25; j += 256) {
            int c = j / 25, tap = j % 25;
            s.dww[tap * 32 + c] = dw_w[(head * KDIM + c) * 25 + tap];
        }
        __syncthreads();

        // ================= qkv GEMM (mma, 3-term, B double-buffered) =================
        {
            float qacc[4][3][4];
            #pragma unroll
            for (int m = 0; m < 4; ++m)
                #pragma unroll
                for (int j = 0; j < 3; ++j)
                    #pragma unroll
                    for (int q = 0; q < 4; ++q) qacc[m][j][q] = 0.f;

            uint2 bhc[3], blc[3];
            #pragma unroll
            for (int j = 0; j < 3; ++j) {
                int bi = ((head * 24 + warp * 3 + j) * 8 + 0) * 32 + lane;
                bhc[j] = g_qwB_hi[bi];
                blc[j] = g_qwB_lo[bi];
            }
            #pragma unroll
            for (int k = 0; k < 8; ++k) {
                uint2 bhn[3], bln[3];
                if (k < 7) {
                    #pragma unroll
                    for (int j = 0; j < 3; ++j) {
                        int bi = ((head * 24 + warp * 3 + j) * 8 + k + 1) * 32 + lane;
                        bhn[j] = g_qwB_hi[bi];
                        bln[j] = g_qwB_lo[bi];
                    }
                }
                #pragma unroll
                for (int m = 0; m < 4; ++m) {
                    unsigned Ah[4], Al[4];
                    ldsm_x4(Ah, s2u(&s.ah[(m * 16 + a_r) * FST + k * 16 + a_c]));
                    ldsm_x4(Al, s2u(&s.al[(m * 16 + a_r) * FST + k * 16 + a_c]));
                    #pragma unroll
                    for (int j = 0; j < 3; ++j) {
                        mma16816(qacc[m][j], Ah, reinterpret_cast<const unsigned*>(&bhc[j]));
                        mma16816(qacc[m][j], Ah, reinterpret_cast<const unsigned*>(&blc[j]));
                        mma16816(qacc[m][j], Al, reinterpret_cast<const unsigned*>(&bhc[j]));
                    }
                }
                if (k < 7) {
                    #pragma unroll
                    for (int j = 0; j < 3; ++j) { bhc[j] = bhn[j]; blc[j] = bln[j]; }
                }
            }
            // epilogue: BN fold -> yq (q fp32) | kh/kl | vh/vl
            #pragma unroll
            for (int m = 0; m < 4; ++m) {
                int rb = m * 16 + (lane >> 2);
                #pragma unroll
                for (int j = 0; j < 3; ++j) {
                    int c0 = warp * 24 + j * 8 + (lane & 3) * 2;
                    float sc0 = s.qscale[c0], sc1 = s.qscale[c0 + 1];
                    float bb0 = s.qbias[c0],  bb1 = s.qbias[c0 + 1];
                    #pragma unroll
                    for (int h2 = 0; h2 < 2; ++h2) {
                        int r = rb + h2 * 8;
                        if (r < NTOK) {
                            float y0 = qacc[m][j][h2 * 2 + 0] * sc0 + bb0;
                            float y1 = qacc[m][j][h2 * 2 + 1] * sc1 + bb1;
                            if (c0 < 32) {
                                s.u2.yq[r * YQS + c0]     = y0;
                                s.u2.yq[r * YQS + c0 + 1] = y1;
                            } else if (c0 < 64) {
                                unsigned hp, lp;
                                split2(y0, y1, hp, lp);
                                *reinterpret_cast<unsigned*>(&s.u1.s1.kh[r * KQS + c0 - 32]) = hp;
                                *reinterpret_cast<unsigned*>(&s.u1.s1.kl[r * KQS + c0 - 32]) = lp;
                            } else {
                                unsigned hp, lp;
                                split2(y0, y1, hp, lp);
                                *reinterpret_cast<unsigned*>(&s.vh[r * FST + c0 - 64]) = hp;
                                *reinterpret_cast<unsigned*>(&s.vl[r * FST + c0 - 64]) = lp;
                            }
                        }
                    }
                }
            }
        }
        __syncthreads();

        // ================= depthwise 5x5 conv (+BN) -> qh/ql =================
        for (int idx = t; idx < NTOK * KDIM; idx += 256) {
            int n = idx >> 5, c = idx & 31;
            int r = n / 7, sc_ = n % 7;
            float sum = 0.f;
            #pragma unroll
            for (int a = 0; a < 5; ++a) {
                int rr = r + a - 2;
                if ((unsigned)rr < 7u) {
                    #pragma unroll
                    for (int bb = 0; bb < 5; ++bb) {
                        int ss = sc_ + bb - 2;
                        if ((unsigned)ss < 7u)
                            sum += s.u2.yq[(rr * 7 + ss) * YQS + c] * s.dww[(a * 5 + bb) * 32 + c];
                    }
                }
            }
            float qv = sum * s.dws[c] + s.dwb[c];
            __nv_bfloat16 hv = __float2bfloat16(qv);
            s.u1.s1.qh[n * KQS + c] = hv;
            s.u1.s1.ql[n * KQS + c] = __float2bfloat16(qv - __bfloat162float(hv));
        }
        __syncthreads();

        // ================= qk scores (mma, 3-term) =================
        {
            const int wm = (warp & 3) * 16, wn = (warp >> 2) * 32;
            float sacc[4][4];
            #pragma unroll
            for (int nt = 0; nt < 4; ++nt)
                #pragma unroll
                for (int q = 0; q < 4; ++q) sacc[nt][q] = 0.f;

            #pragma unroll
            for (int k16 = 0; k16 < 2; ++k16) {
                unsigned Ah[4], Al[4];
                ldsm_x4(Ah, s2u(&s.u1.s1.qh[(wm + a_r) * KQS + k16 * 16 + a_c]));
                ldsm_x4(Al, s2u(&s.u1.s1.ql[(wm + a_r) * KQS + k16 * 16 + a_c]));
                unsigned Bh[2][4], Bl[2][4];
                #pragma unroll
                for (int g = 0; g < 2; ++g) {
                    ldsm_x4(Bh[g], s2u(&s.u1.s1.kh[(wn + g * 16 + b_r) * KQS + k16 * 16 + b_c]));
                    ldsm_x4(Bl[g], s2u(&s.u1.s1.kl[(wn + g * 16 + b_r) * KQS + k16 * 16 + b_c]));
                }
                #pragma unroll
                for (int nt = 0; nt < 4; ++nt) {
                    const unsigned* bh = &Bh[nt >> 1][(nt & 1) * 2];
                    const unsigned* bl = &Bl[nt >> 1][(nt & 1) * 2];
                    mma16816(sacc[nt], Ah, bh);
                    mma16816(sacc[nt], Ah, bl);
                    mma16816(sacc[nt], Al, bh);
                }
            }
            const float* abr = s.ab + head * NTOK;
            int r0 = wm + (lane >> 2);
            #pragma unroll
            for (int nt = 0; nt < 4; ++nt) {
                int c0 = wn + nt * 8 + (lane & 3) * 2;
                #pragma unroll
                for (int h2 = 0; h2 < 2; ++h2) {
                    int r = r0 + h2 * 8;
                    if (r < NTOK) {
                        int rr7 = r / 7, rm7 = r % 7;
                        #pragma unroll
                        for (int q = 0; q < 2; ++q) {
                            int c = c0 + q;
                            if (c < NTOK) {
                                int cd = c / 7, cm = c % 7;
                                int bi = abs(rr7 - cd) * 7 + abs(rm7 - cm);
                                s.u2.attn[r * ASF + c] =
                                    sacc[nt][h2 * 2 + q] * scale + abr[bi];
                            }
                        }
                    }
                }
            }
        }
        __syncthreads();

        // ================= softmax -> ath/atl =================
        for (int r = warp; r < NTOK; r += 8) {
            float a = s.u2.attn[r * ASF + lane];
            bool hasb = (lane + 32) < NTOK;
            float bv = hasb ? s.u2.attn[r * ASF + 32 + lane] : -1e30f;
            float mx = fmaxf(a, bv);
            #pragma unroll
            for (int off = 16; off > 0; off >>= 1)
                mx = fmaxf(mx, __shfl_xor_sync(0xffffffffu, mx, off));
            float ea = __expf(a - mx);
            float eb = hasb ? __expf(bv - mx) : 0.f;
            float sm = ea + eb;
            #pragma unroll
            for (int off = 16; off > 0; off >>= 1)
                sm += __shfl_xor_sync(0xffffffffu, sm, off);
            float inv = __frcp_rn(sm);
            float pa = ea * inv, pb = eb * inv;
            __nv_bfloat16 ph = __float2bfloat16(pa);
            s.u1.s2.ath[r * ATS + lane] = ph;
            s.u1.s2.atl[r * ATS + lane] = __float2bfloat16(pa - __bfloat162float(ph));
            if (hasb) {
                __nv_bfloat16 qh2 = __float2bfloat16(pb);
                s.u1.s2.ath[r * ATS + 32 + lane] = qh2;
                s.u1.s2.atl[r * ATS + 32 + lane] = __float2bfloat16(pb - __bfloat162float(qh2));
            }
            if (lane < 15) {
                __nv_bfloat16 z = __float2bfloat16(0.f);
                s.u1.s2.ath[r * ATS + 49 + lane] = z;
                s.u1.s2.atl[r * ATS + 49 + lane] = z;
            }
        }
        __syncthreads();

        // ================= attn @ v (mma, 3-term) =================
        {
            const int wm2 = (warp & 1) * 32, wn2 = (warp >> 1) * 32;
            float facc[2][4][4];
            #pragma unroll
            for (int mt = 0; mt < 2; ++mt)
                #pragma unroll
                for (int nt = 0; nt < 4; ++nt)
                    #pragma unroll
                    for (int q = 0; q < 4; ++q) facc[mt][nt][q] = 0.f;

            #pragma unroll
            for (int k16 = 0; k16 < 4; ++k16) {
                unsigned Ah[2][4], Al[2][4];
                #pragma unroll
                for (int mt = 0; mt < 2; ++mt) {
                    ldsm_x4(Ah[mt], s2u(&s.u1.s2.ath[(wm2 + mt * 16 + a_r) * ATS + k16 * 16 + a_c]));
                    ldsm_x4(Al[mt], s2u(&s.u1.s2.atl[(wm2 + mt * 16 + a_r) * ATS + k16 * 16 + a_c]));
                }
                unsigned Bh[2][4], Bl[2][4];
                #pragma unroll
                for (int g = 0; g < 2; ++g) {
                    unsigned addr_h = s2u(&s.vh[(k16 * 16 + (lane & 15)) * FST +
                                                wn2 + g * 16 + (lane >> 4) * 8]);
                    unsigned addr_l = s2u(&s.vl[(k16 * 16 + (lane & 15)) * FST +
                                                wn2 + g * 16 + (lane >> 4) * 8]);
                    ldsm_x4_t(Bh[g], addr_h);
                    ldsm_x4_t(Bl[g], addr_l);
                }
                #pragma unroll
                for (int mt = 0; mt < 2; ++mt)
                    #pragma unroll
                    for (int nt = 0; nt < 4; ++nt) {
                        const unsigned* bh = &Bh[nt >> 1][(nt & 1) * 2];
                        const unsigned* bl = &Bl[nt >> 1][(nt & 1) * 2];
                        mma16816(facc[mt][nt], Ah[mt], bh);
                        mma16816(facc[mt][nt], Ah[mt], bl);
                        mma16816(facc[mt][nt], Al[mt], bh);
                    }
            }
            // epilogue: new feat (ah/al) + relu to g_hA (tiled A layout)
            #pragma unroll
            for (int mt = 0; mt < 2; ++mt)
                #pragma unroll
                for (int nt = 0; nt < 4; ++nt) {
                    int c0 = wn2 + nt * 8 + (lane & 3) * 2;
                    int C  = head * 128 + c0;
                    int kstep = C >> 4, jj = C & 15;
                    int quad = (jj < 8) ? (jj >> 1) : ((jj - 8) >> 1);
                    int word = (jj < 8) ? 0 : 1;
                    #pragma unroll
                    for (int h2 = 0; h2 < 2; ++h2) {
                        int r = wm2 + mt * 16 + (lane >> 2) + h2 * 8;
                        if (r < NTOK) {
                            float v0 = facc[mt][nt][h2 * 2 + 0];
                            float v1 = facc[mt][nt][h2 * 2 + 1];
                            unsigned hp, lp;
                            split2(v0, v1, hp, lp);
                            *reinterpret_cast<unsigned*>(&s.ah[r * FST + c0]) = hp;
                            *reinterpret_cast<unsigned*>(&s.al[r * FST + c0]) = lp;
                            float r0v = fmaxf(v0, 0.f), r1v = fmaxf(v1, 0.f);
                            unsigned ghp, glp;
                            split2(r0v, r1v, ghp, glp);
                            size_t row = (size_t)b * NTOK + r;
                            size_t idx = (row >> 4) * 2048 + (size_t)kstep * 64 +
                                         (row & 15) * 4 + quad;
                            unsigned* up = reinterpret_cast<unsigned*>(&g_hA[idx]);
                            up[word]     = ghp;
                            up[word + 2] = glp;
                        }
                    }
                }
        }
        // prefetch next head's x chunk before the barrier
        if (head < NHEADS - 1 && t < 196)
            pref_l1(&x[xoff + (t >> 2) * CH + (head + 1) * 128 + (t & 3) * 32]);
        __syncthreads();
    }
}

// ==================== Phase B: projection — pure LDG + mma ====================

__global__ void __launch_bounds__(256, 2) proj_mma_kernel(
    const float* __restrict__ proj_g, const float* __restrict__ proj_b,
    const float* __restrict__ proj_m, const float* __restrict__ proj_v,
    float* __restrict__ out)
{
    __shared__ float sPs[64], sPb[64];

    const int t = threadIdx.x, lane = t & 31, warp = t >> 5;
    const int row0 = blockIdx.y * 128, col0 = blockIdx.x * 64;

    if (t < 64) {
        int o = col0 + t;
        float sc = proj_g[o] * rsqrtf(proj_v[o] + EPS);
        sPs[t] = sc;
        sPb[t] = proj_b[o] - proj_m[o] * sc;
    }
    __syncthreads();

    const int wm = (warp >> 1) * 32, wn = (warp & 1) * 32;
    const int nb = (col0 >> 3) + (wn >> 3);

    float acc[2][4][4];
    #pragma unroll
    for (int mt = 0; mt < 2; ++mt)
        #pragma unroll
        for (int nt = 0; nt < 4; ++nt)
            #pragma unroll
            for (int q = 0; q < 4; ++q) acc[mt][nt][q] = 0.f;

    const int tile0 = (row0 + wm) >> 4;          // two m16 tiles: tile0, tile0+1

    for (int ks = 0; ks < 32; ++ks) {
        unsigned Ah[2][4], Al[2][4];
        #pragma unroll
        for (int mt = 0; mt < 2; ++mt) {
            size_t base = (size_t)(tile0 + mt) * 2048 + ks * 64;
            uint4 U0 = g_hA[base + lane];        // rows ar   (coalesced 512B)
            uint4 U1 = g_hA[base + 32 + lane];   // rows ar+8 (coalesced 512B)
            Ah[mt][0] = U0.x; Ah[mt][1] = U1.x; Ah[mt][2] = U0.y; Ah[mt][3] = U1.y;
            Al[mt][0] = U0.z; Al[mt][1] = U1.z; Al[mt][2] = U0.w; Al[mt][3] = U1.w;
        }
        uint4 W[4];
        #pragma unroll
        for (int nt = 0; nt < 4; ++nt)
            W[nt] = g_wB[((nb + nt) * 32 + ks) * 32 + lane];

        #pragma unroll
        for (int mt = 0; mt < 2; ++mt)
            #pragma unroll
            for (int nt = 0; nt < 4; ++nt) {
                unsigned bh[2] = {W[nt].x, W[nt].y};
                unsigned bl[2] = {W[nt].z, W[nt].w};
                mma16816(acc[mt][nt], Ah[mt], bh);
                mma16816(acc[mt][nt], Ah[mt], bl);
                mma16816(acc[mt][nt], Al[mt], bh);
            }
    }

    const int er = lane >> 2, ec = (lane & 3) * 2;
    #pragma unroll
    for (int mt = 0; mt < 2; ++mt)
        #pragma unroll
        for (int nt = 0; nt < 4; ++nt) {
            int cl = wn + nt * 8 + ec;
            float s0 = sPs[cl], s1 = sPs[cl + 1];
            float b0 = sPb[cl], b1 = sPb[cl + 1];
            size_t gr = (size_t)(row0 + wm + mt * 16 + er) * 512 + col0 + cl;
            *reinterpret_cast<float2*>(&out[gr]) =
                make_float2(acc[mt][nt][0] * s0 + b0, acc[mt][nt][1] * s1 + b1);
            *reinterpret_cast<float2*>(&out[gr + (size_t)8 * 512]) =
                make_float2(acc[mt][nt][2] * s0 + b0, acc[mt][nt][3] * s1 + b1);
        }
}

// ==================== launch ====================

extern "C" void kernel_launch(void* const* d_in, const int* in_sizes, int n_in,
                              void* d_out, int out_size) {
    const float* x         = (const float*)d_in[0];
    const float* qkv_w     = (const float*)d_in[1];
    const float* qkv_g     = (const float*)d_in[2];
    const float* qkv_b     = (const float*)d_in[3];
    const float* qkv_m     = (const float*)d_in[4];
    const float* qkv_v     = (const float*)d_in[5];
    const float* dw_w      = (const float*)d_in[6];
    const float* dw_g      = (const float*)d_in[7];
    const float* dw_b      = (const float*)d_in[8];
    const float* dw_m      = (const float*)d_in[9];
    const float* dw_v      = (const float*)d_in[10];
    const float* proj_w    = (const float*)d_in[11];
    const float* proj_g    = (const float*)d_in[12];
    const float* proj_b    = (const float*)d_in[13];
    const float* proj_m    = (const float*)d_in[14];
    const float* proj_v    = (const float*)d_in[15];
    const float* attn_bias = (const float*)d_in[16];
    float* out = (float*)d_out;

    cudaFuncSetAttribute(cascade_kernel,
                         cudaFuncAttributeMaxDynamicSharedMemorySize,
                         (int)sizeof(SmemA));

    wsplit_kernel<<<256, 256>>>(proj_w);
    qkvsplit_kernel<<<192, 256>>>(qkv_w);

    cascade_kernel<<<BATCH, 256, sizeof(SmemA)>>>(
        x, qkv_g, qkv_b, qkv_m, qkv_v,
        dw_w, dw_g, dw_b, dw_m, dw_v, attn_bias);

    proj_mma_kernel<<<dim3(8, 784), 256>>>(proj_g, proj_b, proj_m, proj_v, out);
}